// round 6
// baseline (speedup 1.0000x reference)
#include <cuda_runtime.h>
#include <cstdint>

// Problem constants
#define BB   4
#define C3   256
#define H3   48
#define L3   (H3*H3)          // 2304
#define C2   128
#define H2   96
#define L2n  (H2*H2)          // 9216
#define C1   64
#define H1   192
#define L1n  (H1*H1)          // 36864
#define EPSN 1e-12f

#define BK 16

// ---------------- scratch (static device globals; no allocation) -------------
__device__ float g_P[(size_t)BB * L3 * L3];          // [b][lq][lk]  ~85MB
__device__ float g_cl3T[(size_t)BB * L3 * C3];       // [b][pix][c]
__device__ float g_cl2T[(size_t)BB * L2n * C2];
__device__ float g_cl1T[(size_t)BB * L1n * C1];
__device__ float g_sq[2][BB * L3];                    // per-pixel sq-norm: 0=img 1=ref
__device__ float g_nrm[2][BB * L3];                   // 0: nq(img) norm, 1: 1/nk(ref)
__device__ int   g_idx[BB * L3];                      // argmax index per query

// ---------------- helpers -----------------------------------------------------
__device__ __forceinline__ void cp_async16(uint32_t smem, const void* gmem) {
    asm volatile("cp.async.cg.shared.global [%0], [%1], 16;\n" :: "r"(smem), "l"(gmem));
}
__device__ __forceinline__ void cp_commit() {
    asm volatile("cp.async.commit_group;\n" ::: "memory");
}
__device__ __forceinline__ void cp_wait0() {
    asm volatile("cp.async.wait_group 0;\n" ::: "memory");
}
// packed fp32x2 FMA: d = a*b + d  (componentwise, exact fp32 semantics)
__device__ __forceinline__ void fma2(unsigned long long& d, unsigned long long a,
                                     unsigned long long b) {
    asm("fma.rn.f32x2 %0, %1, %2, %0;" : "+l"(d) : "l"(a), "l"(b));
}
__device__ __forceinline__ unsigned long long bcast2(float x) {
    unsigned long long r;
    asm("mov.b64 %0, {%1, %1};" : "=l"(r) : "f"(x));
    return r;
}

// ---------------- 1) per-pixel squared norms ---------------------------------
__global__ void sqsum_kernel(const float* __restrict__ img, const float* __restrict__ ref) {
    int l = blockIdx.x * 256 + threadIdx.x;           // 0..2303
    int b = blockIdx.y;
    int which = blockIdx.z;                           // 0=img 1=ref
    const float* src = (which == 0) ? img : ref;
    src += (size_t)b * C3 * L3 + l;
    float s = 0.f;
    #pragma unroll 4
    for (int c = 0; c < C3; c++) {
        float v = src[(size_t)c * L3];
        s += v * v;
    }
    g_sq[which][b * L3 + l] = s;
}

// ---------------- 2) 3x3 box-sum -> patch norm -------------------------------
__global__ void boxnorm_kernel() {
    int l = blockIdx.x * 256 + threadIdx.x;
    int b = blockIdx.y;
    int which = blockIdx.z;
    int y = l / H3, x = l % H3;
    const float* s = &g_sq[which][b * L3];
    float acc = 0.f;
    #pragma unroll
    for (int dy = -1; dy <= 1; dy++) {
        int yy = y + dy;
        if ((unsigned)yy >= H3) continue;
        #pragma unroll
        for (int dx = -1; dx <= 1; dx++) {
            int xx = x + dx;
            if ((unsigned)xx >= H3) continue;
            acc += s[yy * H3 + xx];
        }
    }
    float n = fmaxf(sqrtf(acc), EPSN);
    g_nrm[which][b * L3 + l] = (which == 1) ? (1.0f / n) : n;
}

// ---------------- 3) transpose cl_ref to channel-last ------------------------
__global__ void transpose_kernel(const float* __restrict__ src, int C, int L, int sel) {
    float* dst = (sel == 0) ? g_cl3T : (sel == 1) ? g_cl2T : g_cl1T;
    __shared__ float tile[32][33];
    int l0 = blockIdx.x * 32, c0 = blockIdx.y * 32, b = blockIdx.z;
    const float* s = src + (size_t)b * C * L;
    float* d = dst + (size_t)b * L * C;
    #pragma unroll
    for (int i = threadIdx.y; i < 32; i += 8)
        tile[i][threadIdx.x] = s[(size_t)(c0 + i) * L + l0 + threadIdx.x];
    __syncthreads();
    #pragma unroll
    for (int i = threadIdx.y; i < 32; i += 8)
        d[(size_t)(l0 + i) * C + c0 + threadIdx.x] = tile[threadIdx.x][i];
}

// ---------------- 4) SGEMM via packed FFMA2 (fma.rn.f32x2) -------------------
// P[b][lq][lk] = sum_c img[c][lq]*ref[c][lk].  128x128 tile, BK=16,
// double-buffered cp.async, 8x8 microtile as 8x(4 packed pairs), 256 threads.
__global__ void __launch_bounds__(256, 2) gemm_kernel(const float* __restrict__ img,
                                                      const float* __restrict__ ref) {
    const int b  = blockIdx.z;
    const int m0 = blockIdx.y * 128;
    const int n0 = blockIdx.x * 128;
    const float* A  = img + (size_t)b * C3 * L3;   // [k][m]
    const float* Bm = ref + (size_t)b * C3 * L3;   // [k][n]
    float* Cc = g_P + (size_t)b * L3 * L3;

    __shared__ __align__(16) float As[2][BK][128];
    __shared__ __align__(16) float Bs[2][BK][128];

    const int tid = threadIdx.x;
    const int lr  = tid >> 5;            // 0..7
    const int lc  = (tid & 31) * 4;      // 0..124
    const int tx  = tid & 15;
    const int ty  = tid >> 4;

    const float* gA0 = &A [(size_t)lr       * L3 + m0 + lc];
    const float* gA1 = &A [(size_t)(lr + 8) * L3 + m0 + lc];
    const float* gB0 = &Bm[(size_t)lr       * L3 + n0 + lc];
    const float* gB1 = &Bm[(size_t)(lr + 8) * L3 + n0 + lc];
    const size_t kstep = (size_t)BK * L3;

    uint32_t sA0[2], sA1[2], sB0[2], sB1[2];
    #pragma unroll
    for (int u = 0; u < 2; u++) {
        sA0[u] = (uint32_t)__cvta_generic_to_shared(&As[u][lr][lc]);
        sA1[u] = (uint32_t)__cvta_generic_to_shared(&As[u][lr + 8][lc]);
        sB0[u] = (uint32_t)__cvta_generic_to_shared(&Bs[u][lr][lc]);
        sB1[u] = (uint32_t)__cvta_generic_to_shared(&Bs[u][lr + 8][lc]);
    }

    unsigned long long acc2[8][4];       // [mi][nj-pair]  (lo = even n)
    #pragma unroll
    for (int i = 0; i < 8; i++)
        #pragma unroll
        for (int j = 0; j < 4; j++) acc2[i][j] = 0ULL;

    // prefetch stage 0
    cp_async16(sA0[0], gA0); cp_async16(sA1[0], gA1);
    cp_async16(sB0[0], gB0); cp_async16(sB1[0], gB1);
    cp_commit();

    int buf = 0;
    for (int k0 = 0; k0 < C3; k0 += BK) {
        cp_wait0();
        __syncthreads();

        if (k0 + BK < C3) {
            size_t off = (size_t)((k0 + BK) / BK) * kstep;
            int nb = buf ^ 1;
            cp_async16(sA0[nb], gA0 + off); cp_async16(sA1[nb], gA1 + off);
            cp_async16(sB0[nb], gB0 + off); cp_async16(sB1[nb], gB1 + off);
            cp_commit();
        }

        #pragma unroll
        for (int kk = 0; kk < BK; kk++) {
            float a[8];
            unsigned long long b2[4];
            *(float4*)&a[0] = *(float4*)&As[buf][kk][ty * 4];
            *(float4*)&a[4] = *(float4*)&As[buf][kk][64 + ty * 4];
            {
                const unsigned long long* p0 =
                    (const unsigned long long*)&Bs[buf][kk][tx * 4];
                const unsigned long long* p1 =
                    (const unsigned long long*)&Bs[buf][kk][64 + tx * 4];
                b2[0] = p0[0]; b2[1] = p0[1];
                b2[2] = p1[0]; b2[3] = p1[1];
            }
            #pragma unroll
            for (int i = 0; i < 8; i++) {
                unsigned long long a2 = bcast2(a[i]);
                fma2(acc2[i][0], a2, b2[0]);
                fma2(acc2[i][1], a2, b2[1]);
                fma2(acc2[i][2], a2, b2[2]);
                fma2(acc2[i][3], a2, b2[3]);
            }
        }
        buf ^= 1;
    }

    // epilogue: 64-bit stores (pairs are contiguous in n)
    #pragma unroll
    for (int i = 0; i < 8; i++) {
        int m = m0 + ((i < 4) ? (ty * 4 + i) : (64 + ty * 4 + i - 4));
        float* row = Cc + (size_t)m * L3;
        *(unsigned long long*)&row[n0 + tx * 4]          = acc2[i][0];
        *(unsigned long long*)&row[n0 + tx * 4 + 2]      = acc2[i][1];
        *(unsigned long long*)&row[n0 + 64 + tx * 4]     = acc2[i][2];
        *(unsigned long long*)&row[n0 + 64 + tx * 4 + 2] = acc2[i][3];
    }
}

// ---------------- 5) shifted-sum + max/argmax over lk ------------------------
__global__ void maxarg_kernel(float* __restrict__ outS) {
    int b = blockIdx.y, lq = blockIdx.x;
    int yq = lq / H3, xq = lq % H3;
    const float* base = g_P + (size_t)b * L3 * L3;

    int  rowOff[9];
    bool qv[9];
    #pragma unroll
    for (int t = 0; t < 9; t++) {
        int di = t / 3 - 1, dj = t % 3 - 1;
        int y2 = yq + di, x2 = xq + dj;
        bool v = ((unsigned)y2 < H3) && ((unsigned)x2 < H3);
        qv[t] = v;
        int d = di * H3 + dj;
        rowOff[t] = v ? (lq + d) * L3 + d : 0;
    }
    const float* rnk = &g_nrm[1][b * L3];   // reciprocal key norms

    float best = -1e30f; int bi = 0;
    for (int lk = threadIdx.x; lk < L3; lk += 256) {
        int yk = lk / H3, xk = lk % H3;
        float s = 0.f;
        #pragma unroll
        for (int t = 0; t < 9; t++) {
            int di = t / 3 - 1, dj = t % 3 - 1;
            if (qv[t] && ((unsigned)(yk + di) < H3) && ((unsigned)(xk + dj) < H3))
                s += base[rowOff[t] + lk];
        }
        float sc = s * rnk[lk];
        if (sc > best) { best = sc; bi = lk; }
    }

    __shared__ float sv[256];
    __shared__ int   si[256];
    sv[threadIdx.x] = best; si[threadIdx.x] = bi;
    __syncthreads();
    for (int st = 128; st > 0; st >>= 1) {
        if (threadIdx.x < st) {
            float o = sv[threadIdx.x + st]; int oi = si[threadIdx.x + st];
            if (o > sv[threadIdx.x] || (o == sv[threadIdx.x] && oi < si[threadIdx.x])) {
                sv[threadIdx.x] = o; si[threadIdx.x] = oi;
            }
        }
        __syncthreads();
    }
    if (threadIdx.x == 0) {
        g_idx[b * L3 + lq] = si[0];
        outS[b * L3 + lq]  = sv[0] / g_nrm[0][b * L3 + lq];
    }
}

// ---------------- 6) fused gather + fold-normalize ---------------------------
__global__ void transfer_kernel(float* __restrict__ out, int C, int W, int s, int sel) {
    const float* clT = (sel == 0) ? g_cl3T : (sel == 1) ? g_cl2T : g_cl1T;
    __shared__ float acc[12288];                 // C*W floats == 48KB for all levels
    int b = blockIdx.y, y = blockIdx.x;
    int tid = threadIdx.x;
    int cid  = tid % C;
    int xsub = tid / C;
    int ppp  = 256 / C;                          // pixels handled in parallel

    int tyq = y / s;
    int yqs[3]; int nvy = 0;
    #pragma unroll
    for (int d = -1; d <= 1; d++) {
        int yq = tyq + d;
        if (0 <= yq && yq < H3) yqs[nvy++] = yq;
    }
    const int* idxb = g_idx + b * L3;
    size_t clb = (size_t)b * W * W * C;

    for (int x0 = 0; x0 < W; x0 += ppp) {
        int x = x0 + xsub;
        int txq = x / s;
        float sum = 0.f; int cnt = 0;
        for (int a = 0; a < nvy; a++) {
            int yq = yqs[a];
            #pragma unroll
            for (int d = -1; d <= 1; d++) {
                int xq = txq + d;
                if ((unsigned)xq >= H3) continue;
                cnt++;
                int idx = idxb[yq * H3 + xq];
                int yk = idx / H3, xk = idx % H3;
                int ys = y + s * (yk - yq);
                int xs = x + s * (xk - xq);
                if ((unsigned)ys < (unsigned)W && (unsigned)xs < (unsigned)W)
                    sum += clT[clb + ((size_t)ys * W + xs) * C + cid];
            }
        }
        acc[cid * W + x] = sum / (float)cnt;
    }
    __syncthreads();

    size_t ob = (size_t)b * C * W * W + (size_t)y * W;
    for (int i = tid; i < C * W; i += 256) {
        int c = i / W, x = i % W;
        out[ob + (size_t)c * W * W + x] = acc[i];
    }
}

// ---------------- launch ------------------------------------------------------
extern "C" void kernel_launch(void* const* d_in, const int* in_sizes, int n_in,
                              void* d_out, int out_size) {
    const float* img = (const float*)d_in[0];   // dh_img_lv3 [4,256,48,48]
    const float* ref = (const float*)d_in[1];   // dh_ref_lv3 [4,256,48,48]
    const float* cl1 = (const float*)d_in[2];   // cl_ref_lv1 [4,64,192,192]
    const float* cl2 = (const float*)d_in[3];   // cl_ref_lv2 [4,128,96,96]
    const float* cl3 = (const float*)d_in[4];   // cl_ref_lv3 [4,256,48,48]

    float* outS  = (float*)d_out;               // [4,1,48,48]
    float* outT3 = outS  + BB * L3;             // [4,256,48,48]
    float* outT2 = outT3 + (size_t)BB * C3 * L3;    // [4,128,96,96]
    float* outT1 = outT2 + (size_t)BB * C2 * L2n;   // [4,64,192,192]

    sqsum_kernel  <<<dim3(9, BB, 2), 256>>>(img, ref);                                // 0
    boxnorm_kernel<<<dim3(9, BB, 2), 256>>>();                                        // 1
    transpose_kernel<<<dim3(L3  / 32, C3 / 32, BB), dim3(32, 8)>>>(cl3, C3, L3,  0);  // 2

    gemm_kernel<<<dim3(L3 / 128, L3 / 128, BB), 256>>>(img, ref);                     // 3 (profiled)

    transpose_kernel<<<dim3(L2n / 32, C2 / 32, BB), dim3(32, 8)>>>(cl2, C2, L2n, 1);  // 4
    transpose_kernel<<<dim3(L1n / 32, C1 / 32, BB), dim3(32, 8)>>>(cl1, C1, L1n, 2);  // 5

    maxarg_kernel<<<dim3(L3, BB), 256>>>(outS);                                       // 6

    transfer_kernel<<<dim3(H3, BB), 256>>>(outT3, C3, H3, 1, 0);                      // 7
    transfer_kernel<<<dim3(H2, BB), 256>>>(outT2, C2, H2, 2, 1);                      // 8
    transfer_kernel<<<dim3(H1, BB), 256>>>(outT1, C1, H1, 4, 2);                      // 9
}

// round 7
// speedup vs baseline: 1.3936x; 1.3936x over previous
#include <cuda_runtime.h>
#include <cstdint>

// Problem constants
#define BB   4
#define C3   256
#define H3   48
#define L3   (H3*H3)          // 2304
#define C2   128
#define H2   96
#define L2n  (H2*H2)          // 9216
#define C1   64
#define H1   192
#define L1n  (H1*H1)          // 36864
#define EPSN 1e-12f

#define BK 16

// ---------------- scratch (static device globals; no allocation) -------------
__device__ float g_P[(size_t)BB * L3 * L3];          // [b][lq][lk]  ~85MB
__device__ float g_cl3T[(size_t)BB * L3 * C3];       // [b][pix][c]
__device__ float g_cl2T[(size_t)BB * L2n * C2];
__device__ float g_cl1T[(size_t)BB * L1n * C1];
__device__ float g_sq[2][BB * L3];                    // per-pixel sq-norm: 0=img 1=ref
__device__ float g_nrm[2][BB * L3];                   // 0: nq(img) norm, 1: 1/nk(ref)
__device__ int   g_idx[BB * L3];                      // argmax index per query
__device__ float g_zero[L3 + 128];                    // stays zero (zero-init, never written)

// ---------------- helpers -----------------------------------------------------
__device__ __forceinline__ void cp_async16(uint32_t smem, const void* gmem) {
    asm volatile("cp.async.cg.shared.global [%0], [%1], 16;\n" :: "r"(smem), "l"(gmem));
}
__device__ __forceinline__ void cp_commit() {
    asm volatile("cp.async.commit_group;\n" ::: "memory");
}
__device__ __forceinline__ void cp_wait0() {
    asm volatile("cp.async.wait_group 0;\n" ::: "memory");
}
// packed fp32x2 FMA: d = a*b + d  (componentwise, exact fp32 semantics)
__device__ __forceinline__ void fma2(unsigned long long& d, unsigned long long a,
                                     unsigned long long b) {
    asm("fma.rn.f32x2 %0, %1, %2, %0;" : "+l"(d) : "l"(a), "l"(b));
}
__device__ __forceinline__ unsigned long long bcast2(float x) {
    unsigned long long r;
    asm("mov.b64 %0, {%1, %1};" : "=l"(r) : "f"(x));
    return r;
}

// ---------------- 1) per-pixel squared norms ---------------------------------
__global__ void sqsum_kernel(const float* __restrict__ img, const float* __restrict__ ref) {
    int l = blockIdx.x * 256 + threadIdx.x;           // 0..2303
    int b = blockIdx.y;
    int which = blockIdx.z;                           // 0=img 1=ref
    const float* src = (which == 0) ? img : ref;
    src += (size_t)b * C3 * L3 + l;
    float s = 0.f;
    #pragma unroll 4
    for (int c = 0; c < C3; c++) {
        float v = src[(size_t)c * L3];
        s += v * v;
    }
    g_sq[which][b * L3 + l] = s;
}

// ---------------- 2) 3x3 box-sum -> patch norm -------------------------------
__global__ void boxnorm_kernel() {
    int l = blockIdx.x * 256 + threadIdx.x;
    int b = blockIdx.y;
    int which = blockIdx.z;
    int y = l / H3, x = l % H3;
    const float* s = &g_sq[which][b * L3];
    float acc = 0.f;
    #pragma unroll
    for (int dy = -1; dy <= 1; dy++) {
        int yy = y + dy;
        if ((unsigned)yy >= H3) continue;
        #pragma unroll
        for (int dx = -1; dx <= 1; dx++) {
            int xx = x + dx;
            if ((unsigned)xx >= H3) continue;
            acc += s[yy * H3 + xx];
        }
    }
    float n = fmaxf(sqrtf(acc), EPSN);
    g_nrm[which][b * L3 + l] = (which == 1) ? (1.0f / n) : n;
}

// ---------------- 3) transpose cl_ref to channel-last ------------------------
__global__ void transpose_kernel(const float* __restrict__ src, int C, int L, int sel) {
    float* dst = (sel == 0) ? g_cl3T : (sel == 1) ? g_cl2T : g_cl1T;
    __shared__ float tile[32][33];
    int l0 = blockIdx.x * 32, c0 = blockIdx.y * 32, b = blockIdx.z;
    const float* s = src + (size_t)b * C * L;
    float* d = dst + (size_t)b * L * C;
    #pragma unroll
    for (int i = threadIdx.y; i < 32; i += 8)
        tile[i][threadIdx.x] = s[(size_t)(c0 + i) * L + l0 + threadIdx.x];
    __syncthreads();
    #pragma unroll
    for (int i = threadIdx.y; i < 32; i += 8)
        d[(size_t)(l0 + i) * C + c0 + threadIdx.x] = tile[threadIdx.x][i];
}

// ---------------- 4) SGEMM via packed FFMA2 (fma.rn.f32x2) -------------------
__global__ void __launch_bounds__(256, 2) gemm_kernel(const float* __restrict__ img,
                                                      const float* __restrict__ ref) {
    const int b  = blockIdx.z;
    const int m0 = blockIdx.y * 128;
    const int n0 = blockIdx.x * 128;
    const float* A  = img + (size_t)b * C3 * L3;   // [k][m]
    const float* Bm = ref + (size_t)b * C3 * L3;   // [k][n]
    float* Cc = g_P + (size_t)b * L3 * L3;

    __shared__ __align__(16) float As[2][BK][128];
    __shared__ __align__(16) float Bs[2][BK][128];

    const int tid = threadIdx.x;
    const int lr  = tid >> 5;
    const int lc  = (tid & 31) * 4;
    const int tx  = tid & 15;
    const int ty  = tid >> 4;

    const float* gA0 = &A [(size_t)lr       * L3 + m0 + lc];
    const float* gA1 = &A [(size_t)(lr + 8) * L3 + m0 + lc];
    const float* gB0 = &Bm[(size_t)lr       * L3 + n0 + lc];
    const float* gB1 = &Bm[(size_t)(lr + 8) * L3 + n0 + lc];
    const size_t kstep = (size_t)BK * L3;

    uint32_t sA0[2], sA1[2], sB0[2], sB1[2];
    #pragma unroll
    for (int u = 0; u < 2; u++) {
        sA0[u] = (uint32_t)__cvta_generic_to_shared(&As[u][lr][lc]);
        sA1[u] = (uint32_t)__cvta_generic_to_shared(&As[u][lr + 8][lc]);
        sB0[u] = (uint32_t)__cvta_generic_to_shared(&Bs[u][lr][lc]);
        sB1[u] = (uint32_t)__cvta_generic_to_shared(&Bs[u][lr + 8][lc]);
    }

    unsigned long long acc2[8][4];
    #pragma unroll
    for (int i = 0; i < 8; i++)
        #pragma unroll
        for (int j = 0; j < 4; j++) acc2[i][j] = 0ULL;

    cp_async16(sA0[0], gA0); cp_async16(sA1[0], gA1);
    cp_async16(sB0[0], gB0); cp_async16(sB1[0], gB1);
    cp_commit();

    int buf = 0;
    for (int k0 = 0; k0 < C3; k0 += BK) {
        cp_wait0();
        __syncthreads();

        if (k0 + BK < C3) {
            size_t off = (size_t)((k0 + BK) / BK) * kstep;
            int nb = buf ^ 1;
            cp_async16(sA0[nb], gA0 + off); cp_async16(sA1[nb], gA1 + off);
            cp_async16(sB0[nb], gB0 + off); cp_async16(sB1[nb], gB1 + off);
            cp_commit();
        }

        #pragma unroll
        for (int kk = 0; kk < BK; kk++) {
            float a[8];
            unsigned long long b2[4];
            *(float4*)&a[0] = *(float4*)&As[buf][kk][ty * 4];
            *(float4*)&a[4] = *(float4*)&As[buf][kk][64 + ty * 4];
            {
                const unsigned long long* p0 =
                    (const unsigned long long*)&Bs[buf][kk][tx * 4];
                const unsigned long long* p1 =
                    (const unsigned long long*)&Bs[buf][kk][64 + tx * 4];
                b2[0] = p0[0]; b2[1] = p0[1];
                b2[2] = p1[0]; b2[3] = p1[1];
            }
            #pragma unroll
            for (int i = 0; i < 8; i++) {
                unsigned long long a2 = bcast2(a[i]);
                fma2(acc2[i][0], a2, b2[0]);
                fma2(acc2[i][1], a2, b2[1]);
                fma2(acc2[i][2], a2, b2[2]);
                fma2(acc2[i][3], a2, b2[3]);
            }
        }
        buf ^= 1;
    }

    #pragma unroll
    for (int i = 0; i < 8; i++) {
        int m = m0 + ((i < 4) ? (ty * 4 + i) : (64 + ty * 4 + i - 4));
        float* row = Cc + (size_t)m * L3;
        *(unsigned long long*)&row[n0 + tx * 4]          = acc2[i][0];
        *(unsigned long long*)&row[n0 + tx * 4 + 2]      = acc2[i][1];
        *(unsigned long long*)&row[n0 + 64 + tx * 4]     = acc2[i][2];
        *(unsigned long long*)&row[n0 + 64 + tx * 4 + 2] = acc2[i][3];
    }
}

// ---------------- 5) shifted-sum + max/argmax over lk ------------------------
// Query-side invalid shifts -> pointer to a permanent zero row (no branches).
// Key-side: interior fast path (yk,xk in [1,46]) = 9 unconditional adds.
__global__ void maxarg_kernel(float* __restrict__ outS) {
    int b = blockIdx.y, lq = blockIdx.x;
    int yq = lq / H3, xq = lq % H3;
    const float* base  = g_P + (size_t)b * L3 * L3;
    const float* zbase = g_zero + 64;

    const float* rows[9];
    #pragma unroll
    for (int t = 0; t < 9; t++) {
        int di = t / 3 - 1, dj = t % 3 - 1;
        int y2 = yq + di, x2 = xq + dj;
        int d = di * H3 + dj;
        bool v = ((unsigned)y2 < H3) && ((unsigned)x2 < H3);
        rows[t] = v ? (base + (size_t)(lq + d) * L3 + d) : (zbase + d);
    }
    const float* rnk = &g_nrm[1][b * L3];

    float best = -1e30f; int bi = 0;
    int yk = (int)threadIdx.x / H3;
    int xk = (int)threadIdx.x % H3;
    for (int lk = threadIdx.x; lk < L3; lk += 256) {
        float s = 0.f;
        if (yk >= 1 && yk <= 46 && xk >= 1 && xk <= 46) {
            #pragma unroll
            for (int t = 0; t < 9; t++) s += rows[t][lk];
        } else {
            #pragma unroll
            for (int t = 0; t < 9; t++) {
                int di = t / 3 - 1, dj = t % 3 - 1;
                if (((unsigned)(yk + di) < H3) && ((unsigned)(xk + dj) < H3))
                    s += rows[t][lk];
            }
        }
        float sc = s * rnk[lk];
        if (sc > best) { best = sc; bi = lk; }
        xk += 16; yk += 5;
        if (xk >= H3) { xk -= H3; yk += 1; }
    }

    __shared__ float sv[256];
    __shared__ int   si[256];
    sv[threadIdx.x] = best; si[threadIdx.x] = bi;
    __syncthreads();
    for (int st = 128; st > 0; st >>= 1) {
        if (threadIdx.x < st) {
            float o = sv[threadIdx.x + st]; int oi = si[threadIdx.x + st];
            if (o > sv[threadIdx.x] || (o == sv[threadIdx.x] && oi < si[threadIdx.x])) {
                sv[threadIdx.x] = o; si[threadIdx.x] = oi;
            }
        }
        __syncthreads();
    }
    if (threadIdx.x == 0) {
        g_idx[b * L3 + lq] = si[0];
        outS[b * L3 + lq]  = sv[0] / g_nrm[0][b * L3 + lq];
    }
}

// ---------------- 6) fused gather + fold-normalize (x-chunked) ---------------
// grid = (W, BB, NCH); each block covers xpc = W/NCH output pixels of row y.
__global__ void transfer_kernel(float* __restrict__ out, int C, int W, int s, int sel,
                                int xpc) {
    const float* clT = (sel == 0) ? g_cl3T : (sel == 1) ? g_cl2T : g_cl1T;
    __shared__ float acc[3072];                  // C * xpc == 3072 for all levels
    int b = blockIdx.y, y = blockIdx.x;
    int xlo = blockIdx.z * xpc;
    int tid = threadIdx.x;
    int cid  = tid % C;
    int xsub = tid / C;
    int ppp  = 256 / C;

    int tyq = y / s;
    int yqs[3]; int nvy = 0;
    #pragma unroll
    for (int d = -1; d <= 1; d++) {
        int yq = tyq + d;
        if (0 <= yq && yq < H3) yqs[nvy++] = yq;
    }
    const int* idxb = g_idx + b * L3;
    size_t clb = (size_t)b * W * W * C;

    for (int xo = 0; xo < xpc; xo += ppp) {
        int x = xlo + xo + xsub;
        int txq = x / s;
        float sum = 0.f; int cnt = 0;
        for (int a = 0; a < nvy; a++) {
            int yq = yqs[a];
            #pragma unroll
            for (int d = -1; d <= 1; d++) {
                int xq = txq + d;
                if ((unsigned)xq >= H3) continue;
                cnt++;
                int idx = idxb[yq * H3 + xq];
                int yk = idx / H3, xk = idx % H3;
                int ys = y + s * (yk - yq);
                int xs = x + s * (xk - xq);
                if ((unsigned)ys < (unsigned)W && (unsigned)xs < (unsigned)W)
                    sum += clT[clb + ((size_t)ys * W + xs) * C + cid];
            }
        }
        acc[cid * xpc + xo + xsub] = sum / (float)cnt;
    }
    __syncthreads();

    size_t ob = (size_t)b * C * W * W + (size_t)y * W + xlo;
    for (int i = tid; i < C * xpc; i += 256) {
        int c = i / xpc, x = i % xpc;
        out[ob + (size_t)c * W * W + x] = acc[i];
    }
}

// ---------------- launch ------------------------------------------------------
extern "C" void kernel_launch(void* const* d_in, const int* in_sizes, int n_in,
                              void* d_out, int out_size) {
    const float* img = (const float*)d_in[0];   // dh_img_lv3 [4,256,48,48]
    const float* ref = (const float*)d_in[1];   // dh_ref_lv3 [4,256,48,48]
    const float* cl1 = (const float*)d_in[2];   // cl_ref_lv1 [4,64,192,192]
    const float* cl2 = (const float*)d_in[3];   // cl_ref_lv2 [4,128,96,96]
    const float* cl3 = (const float*)d_in[4];   // cl_ref_lv3 [4,256,48,48]

    float* outS  = (float*)d_out;               // [4,1,48,48]
    float* outT3 = outS  + BB * L3;             // [4,256,48,48]
    float* outT2 = outT3 + (size_t)BB * C3 * L3;    // [4,128,96,96]
    float* outT1 = outT2 + (size_t)BB * C2 * L2n;   // [4,64,192,192]

    gemm_kernel<<<dim3(L3 / 128, L3 / 128, BB), 256>>>(img, ref);                     // 0
    sqsum_kernel  <<<dim3(9, BB, 2), 256>>>(img, ref);                                // 1
    boxnorm_kernel<<<dim3(9, BB, 2), 256>>>();                                        // 2

    maxarg_kernel<<<dim3(L3, BB), 256>>>(outS);                                       // 3 (profiled)

    transpose_kernel<<<dim3(L3  / 32, C3 / 32, BB), dim3(32, 8)>>>(cl3, C3, L3,  0);  // 4
    transpose_kernel<<<dim3(L2n / 32, C2 / 32, BB), dim3(32, 8)>>>(cl2, C2, L2n, 1);  // 5
    transpose_kernel<<<dim3(L1n / 32, C1 / 32, BB), dim3(32, 8)>>>(cl1, C1, L1n, 2);  // 6

    transfer_kernel<<<dim3(H3, BB, 4), 256>>>(outT3, C3, H3, 1, 0, H3 / 4);           // 7
    transfer_kernel<<<dim3(H2, BB, 4), 256>>>(outT2, C2, H2, 2, 1, H2 / 4);           // 8
    transfer_kernel<<<dim3(H1, BB, 4), 256>>>(outT1, C1, H1, 4, 2, H1 / 4);           // 9
}

// round 8
// speedup vs baseline: 1.9054x; 1.3672x over previous
#include <cuda_runtime.h>
#include <cstdint>

// Problem constants
#define BB   4
#define C3   256
#define H3   48
#define L3   (H3*H3)          // 2304
#define C2   128
#define H2   96
#define L2n  (H2*H2)          // 9216
#define C1   64
#define H1   192
#define L1n  (H1*H1)          // 36864
#define EPSN 1e-12f

#define BK 16

// ---------------- scratch (static device globals; no allocation) -------------
__device__ float g_P[(size_t)BB * L3 * L3];          // [b][lq][lk]  ~85MB
__device__ float g_cl3T[(size_t)BB * L3 * C3];       // [b][pix][c]
__device__ float g_cl2T[(size_t)BB * L2n * C2];
__device__ float g_cl1T[(size_t)BB * L1n * C1];
__device__ float g_sq[2][BB * L3];                    // per-pixel sq-norm: 0=img 1=ref
__device__ float g_nrm[2][BB * L3];                   // 0: nq(img) norm, 1: 1/nk(ref)
__device__ int   g_idx[BB * L3];                      // argmax index per query
__device__ float g_zero[L3 + 128];                    // stays zero (zero-init, never written)

// ---------------- helpers -----------------------------------------------------
__device__ __forceinline__ void cp_async16(uint32_t smem, const void* gmem) {
    asm volatile("cp.async.cg.shared.global [%0], [%1], 16;\n" :: "r"(smem), "l"(gmem));
}
__device__ __forceinline__ void cp_commit() {
    asm volatile("cp.async.commit_group;\n" ::: "memory");
}
__device__ __forceinline__ void cp_wait0() {
    asm volatile("cp.async.wait_group 0;\n" ::: "memory");
}
// packed fp32x2 FMA: d = a*b + d  (componentwise, exact fp32 semantics)
__device__ __forceinline__ void fma2(unsigned long long& d, unsigned long long a,
                                     unsigned long long b) {
    asm("fma.rn.f32x2 %0, %1, %2, %0;" : "+l"(d) : "l"(a), "l"(b));
}
__device__ __forceinline__ unsigned long long bcast2(float x) {
    unsigned long long r;
    asm("mov.b64 %0, {%1, %1};" : "=l"(r) : "f"(x));
    return r;
}

// ---------------- 1) per-pixel squared norms ---------------------------------
__global__ void sqsum_kernel(const float* __restrict__ img, const float* __restrict__ ref) {
    int l = blockIdx.x * 256 + threadIdx.x;           // 0..2303
    int b = blockIdx.y;
    int which = blockIdx.z;                           // 0=img 1=ref
    const float* src = (which == 0) ? img : ref;
    src += (size_t)b * C3 * L3 + l;
    float s = 0.f;
    #pragma unroll 4
    for (int c = 0; c < C3; c++) {
        float v = src[(size_t)c * L3];
        s += v * v;
    }
    g_sq[which][b * L3 + l] = s;
}

// ---------------- 2) 3x3 box-sum -> patch norm -------------------------------
__global__ void boxnorm_kernel() {
    int l = blockIdx.x * 256 + threadIdx.x;
    int b = blockIdx.y;
    int which = blockIdx.z;
    int y = l / H3, x = l % H3;
    const float* s = &g_sq[which][b * L3];
    float acc = 0.f;
    #pragma unroll
    for (int dy = -1; dy <= 1; dy++) {
        int yy = y + dy;
        if ((unsigned)yy >= H3) continue;
        #pragma unroll
        for (int dx = -1; dx <= 1; dx++) {
            int xx = x + dx;
            if ((unsigned)xx >= H3) continue;
            acc += s[yy * H3 + xx];
        }
    }
    float n = fmaxf(sqrtf(acc), EPSN);
    g_nrm[which][b * L3 + l] = (which == 1) ? (1.0f / n) : n;
}

// ---------------- 3) transpose cl_ref to channel-last ------------------------
__global__ void transpose_kernel(const float* __restrict__ src, int C, int L, int sel) {
    float* dst = (sel == 0) ? g_cl3T : (sel == 1) ? g_cl2T : g_cl1T;
    __shared__ float tile[32][33];
    int l0 = blockIdx.x * 32, c0 = blockIdx.y * 32, b = blockIdx.z;
    const float* s = src + (size_t)b * C * L;
    float* d = dst + (size_t)b * L * C;
    #pragma unroll
    for (int i = threadIdx.y; i < 32; i += 8)
        tile[i][threadIdx.x] = s[(size_t)(c0 + i) * L + l0 + threadIdx.x];
    __syncthreads();
    #pragma unroll
    for (int i = threadIdx.y; i < 32; i += 8)
        d[(size_t)(l0 + i) * C + c0 + threadIdx.x] = tile[threadIdx.x][i];
}

// ---------------- 4) SGEMM via packed FFMA2 (fma.rn.f32x2) -------------------
__global__ void __launch_bounds__(256, 2) gemm_kernel(const float* __restrict__ img,
                                                      const float* __restrict__ ref) {
    const int b  = blockIdx.z;
    const int m0 = blockIdx.y * 128;
    const int n0 = blockIdx.x * 128;
    const float* A  = img + (size_t)b * C3 * L3;   // [k][m]
    const float* Bm = ref + (size_t)b * C3 * L3;   // [k][n]
    float* Cc = g_P + (size_t)b * L3 * L3;

    __shared__ __align__(16) float As[2][BK][128];
    __shared__ __align__(16) float Bs[2][BK][128];

    const int tid = threadIdx.x;
    const int lr  = tid >> 5;
    const int lc  = (tid & 31) * 4;
    const int tx  = tid & 15;
    const int ty  = tid >> 4;

    const float* gA0 = &A [(size_t)lr       * L3 + m0 + lc];
    const float* gA1 = &A [(size_t)(lr + 8) * L3 + m0 + lc];
    const float* gB0 = &Bm[(size_t)lr       * L3 + n0 + lc];
    const float* gB1 = &Bm[(size_t)(lr + 8) * L3 + n0 + lc];
    const size_t kstep = (size_t)BK * L3;

    uint32_t sA0[2], sA1[2], sB0[2], sB1[2];
    #pragma unroll
    for (int u = 0; u < 2; u++) {
        sA0[u] = (uint32_t)__cvta_generic_to_shared(&As[u][lr][lc]);
        sA1[u] = (uint32_t)__cvta_generic_to_shared(&As[u][lr + 8][lc]);
        sB0[u] = (uint32_t)__cvta_generic_to_shared(&Bs[u][lr][lc]);
        sB1[u] = (uint32_t)__cvta_generic_to_shared(&Bs[u][lr + 8][lc]);
    }

    unsigned long long acc2[8][4];
    #pragma unroll
    for (int i = 0; i < 8; i++)
        #pragma unroll
        for (int j = 0; j < 4; j++) acc2[i][j] = 0ULL;

    cp_async16(sA0[0], gA0); cp_async16(sA1[0], gA1);
    cp_async16(sB0[0], gB0); cp_async16(sB1[0], gB1);
    cp_commit();

    int buf = 0;
    for (int k0 = 0; k0 < C3; k0 += BK) {
        cp_wait0();
        __syncthreads();

        if (k0 + BK < C3) {
            size_t off = (size_t)((k0 + BK) / BK) * kstep;
            int nb = buf ^ 1;
            cp_async16(sA0[nb], gA0 + off); cp_async16(sA1[nb], gA1 + off);
            cp_async16(sB0[nb], gB0 + off); cp_async16(sB1[nb], gB1 + off);
            cp_commit();
        }

        #pragma unroll
        for (int kk = 0; kk < BK; kk++) {
            float a[8];
            unsigned long long b2[4];
            *(float4*)&a[0] = *(float4*)&As[buf][kk][ty * 4];
            *(float4*)&a[4] = *(float4*)&As[buf][kk][64 + ty * 4];
            {
                const unsigned long long* p0 =
                    (const unsigned long long*)&Bs[buf][kk][tx * 4];
                const unsigned long long* p1 =
                    (const unsigned long long*)&Bs[buf][kk][64 + tx * 4];
                b2[0] = p0[0]; b2[1] = p0[1];
                b2[2] = p1[0]; b2[3] = p1[1];
            }
            #pragma unroll
            for (int i = 0; i < 8; i++) {
                unsigned long long a2 = bcast2(a[i]);
                fma2(acc2[i][0], a2, b2[0]);
                fma2(acc2[i][1], a2, b2[1]);
                fma2(acc2[i][2], a2, b2[2]);
                fma2(acc2[i][3], a2, b2[3]);
            }
        }
        buf ^= 1;
    }

    #pragma unroll
    for (int i = 0; i < 8; i++) {
        int m = m0 + ((i < 4) ? (ty * 4 + i) : (64 + ty * 4 + i - 4));
        float* row = Cc + (size_t)m * L3;
        *(unsigned long long*)&row[n0 + tx * 4]          = acc2[i][0];
        *(unsigned long long*)&row[n0 + tx * 4 + 2]      = acc2[i][1];
        *(unsigned long long*)&row[n0 + 64 + tx * 4]     = acc2[i][2];
        *(unsigned long long*)&row[n0 + 64 + tx * 4 + 2] = acc2[i][3];
    }
}

// ---------------- 5) shifted-sum + max/argmax over lk ------------------------
__global__ void maxarg_kernel(float* __restrict__ outS) {
    int b = blockIdx.y, lq = blockIdx.x;
    int yq = lq / H3, xq = lq % H3;
    const float* base  = g_P + (size_t)b * L3 * L3;
    const float* zbase = g_zero + 64;

    const float* rows[9];
    #pragma unroll
    for (int t = 0; t < 9; t++) {
        int di = t / 3 - 1, dj = t % 3 - 1;
        int y2 = yq + di, x2 = xq + dj;
        int d = di * H3 + dj;
        bool v = ((unsigned)y2 < H3) && ((unsigned)x2 < H3);
        rows[t] = v ? (base + (size_t)(lq + d) * L3 + d) : (zbase + d);
    }
    const float* rnk = &g_nrm[1][b * L3];

    float best = -1e30f; int bi = 0;
    int yk = (int)threadIdx.x / H3;
    int xk = (int)threadIdx.x % H3;
    for (int lk = threadIdx.x; lk < L3; lk += 256) {
        float s = 0.f;
        if (yk >= 1 && yk <= 46 && xk >= 1 && xk <= 46) {
            #pragma unroll
            for (int t = 0; t < 9; t++) s += rows[t][lk];
        } else {
            #pragma unroll
            for (int t = 0; t < 9; t++) {
                int di = t / 3 - 1, dj = t % 3 - 1;
                if (((unsigned)(yk + di) < H3) && ((unsigned)(xk + dj) < H3))
                    s += rows[t][lk];
            }
        }
        float sc = s * rnk[lk];
        if (sc > best) { best = sc; bi = lk; }
        xk += 16; yk += 5;
        if (xk >= H3) { xk -= H3; yk += 1; }
    }

    __shared__ float sv[256];
    __shared__ int   si[256];
    sv[threadIdx.x] = best; si[threadIdx.x] = bi;
    __syncthreads();
    for (int st = 128; st > 0; st >>= 1) {
        if (threadIdx.x < st) {
            float o = sv[threadIdx.x + st]; int oi = si[threadIdx.x + st];
            if (o > sv[threadIdx.x] || (o == sv[threadIdx.x] && oi < si[threadIdx.x])) {
                sv[threadIdx.x] = o; si[threadIdx.x] = oi;
            }
        }
        __syncthreads();
    }
    if (threadIdx.x == 0) {
        g_idx[b * L3 + lq] = si[0];
        outS[b * L3 + lq]  = sv[0] / g_nrm[0][b * L3 + lq];
    }
}

// ---------------- 6) fused gather + fold-normalize (float4 channel groups) ---
// grid = (W, BB, 4); each block covers xpc = W/4 pixels of row y.
// Thread owns 4 channels (cg) of one pixel slot; gathers are 16B vector loads.
__global__ void transfer_kernel(float* __restrict__ out, int C, int W, int s, int sel,
                                int xpc) {
    const float* clT = (sel == 0) ? g_cl3T : (sel == 1) ? g_cl2T : g_cl1T;
    __shared__ __align__(16) float acc[3456];    // xpc*(C+8) <= 3456 floats
    int b = blockIdx.y, y = blockIdx.x;
    int xlo = blockIdx.z * xpc;
    int tid = threadIdx.x;
    int cpg  = C >> 2;                           // channel groups (threads per pixel)
    int cg   = tid % cpg;
    int xsub = tid / cpg;
    int ppp  = 256 / cpg;                        // pixels handled in parallel
    int astr = C + 8;                            // smem row stride (floats)

    int tyq = y / s;
    int yqs[3]; int nvy = 0;
    #pragma unroll
    for (int d = -1; d <= 1; d++) {
        int yq = tyq + d;
        if (0 <= yq && yq < H3) yqs[nvy++] = yq;
    }
    const int* idxb = g_idx + b * L3;
    size_t clb = (size_t)b * W * W * C + (size_t)cg * 4;

    for (int xo = 0; xo < xpc; xo += ppp) {
        int x = xlo + xo + xsub;
        int txq = x / s;
        float4 sum = make_float4(0.f, 0.f, 0.f, 0.f);
        int cnt = 0;
        for (int a = 0; a < nvy; a++) {
            int yq = yqs[a];
            #pragma unroll
            for (int d = -1; d <= 1; d++) {
                int xq = txq + d;
                if ((unsigned)xq >= H3) continue;
                cnt++;
                int idx = idxb[yq * H3 + xq];
                int yk = idx / H3, xk = idx % H3;
                int ys = y + s * (yk - yq);
                int xs = x + s * (xk - xq);
                if ((unsigned)ys < (unsigned)W && (unsigned)xs < (unsigned)W) {
                    const float4 v = *(const float4*)&clT[clb + ((size_t)ys * W + xs) * C];
                    sum.x += v.x; sum.y += v.y; sum.z += v.z; sum.w += v.w;
                }
            }
        }
        float inv = 1.0f / (float)cnt;
        *(float4*)&acc[(xo + xsub) * astr + cg * 4] =
            make_float4(sum.x * inv, sum.y * inv, sum.z * inv, sum.w * inv);
    }
    __syncthreads();

    size_t ob = (size_t)b * C * W * W + (size_t)y * W + xlo;
    int tot = C * xpc;                           // == 3072 for all levels
    for (int i = tid; i < tot; i += 256) {
        int c = i / xpc, x = i % xpc;
        out[ob + (size_t)c * W * W + x] = acc[x * astr + c];
    }
}

// ---------------- launch ------------------------------------------------------
extern "C" void kernel_launch(void* const* d_in, const int* in_sizes, int n_in,
                              void* d_out, int out_size) {
    const float* img = (const float*)d_in[0];   // dh_img_lv3 [4,256,48,48]
    const float* ref = (const float*)d_in[1];   // dh_ref_lv3 [4,256,48,48]
    const float* cl1 = (const float*)d_in[2];   // cl_ref_lv1 [4,64,192,192]
    const float* cl2 = (const float*)d_in[3];   // cl_ref_lv2 [4,128,96,96]
    const float* cl3 = (const float*)d_in[4];   // cl_ref_lv3 [4,256,48,48]

    float* outS  = (float*)d_out;               // [4,1,48,48]
    float* outT3 = outS  + BB * L3;             // [4,256,48,48]
    float* outT2 = outT3 + (size_t)BB * C3 * L3;    // [4,128,96,96]
    float* outT1 = outT2 + (size_t)BB * C2 * L2n;   // [4,64,192,192]

    gemm_kernel<<<dim3(L3 / 128, L3 / 128, BB), 256>>>(img, ref);                     // 0
    sqsum_kernel  <<<dim3(9, BB, 2), 256>>>(img, ref);                                // 1
    boxnorm_kernel<<<dim3(9, BB, 2), 256>>>();                                        // 2

    maxarg_kernel<<<dim3(L3, BB), 256>>>(outS);                                       // 3 (profiled)

    transpose_kernel<<<dim3(L3  / 32, C3 / 32, BB), dim3(32, 8)>>>(cl3, C3, L3,  0);  // 4
    transpose_kernel<<<dim3(L2n / 32, C2 / 32, BB), dim3(32, 8)>>>(cl2, C2, L2n, 1);  // 5
    transpose_kernel<<<dim3(L1n / 32, C1 / 32, BB), dim3(32, 8)>>>(cl1, C1, L1n, 2);  // 6

    transfer_kernel<<<dim3(H3, BB, 4), 256>>>(outT3, C3, H3, 1, 0, H3 / 4);           // 7
    transfer_kernel<<<dim3(H2, BB, 4), 256>>>(outT2, C2, H2, 2, 1, H2 / 4);           // 8
    transfer_kernel<<<dim3(H1, BB, 4), 256>>>(outT1, C1, H1, 4, 2, H1 / 4);           // 9
}

// round 9
// speedup vs baseline: 2.2272x; 1.1689x over previous
#include <cuda_runtime.h>
#include <cstdint>

// Problem constants
#define BB   4
#define C3   256
#define H3   48
#define L3   (H3*H3)          // 2304
#define C2   128
#define H2   96
#define L2n  (H2*H2)          // 9216
#define C1   64
#define H1   192
#define L1n  (H1*H1)          // 36864
#define EPSN 1e-12f

#define BK 16

// ---------------- scratch (static device globals; no allocation) -------------
__device__ __align__(16) float g_P[(size_t)BB * L3 * L3];   // [b][lq][lk]  ~85MB
__device__ __align__(16) float g_G[(size_t)BB * L3 * L3];   // x-pass of shifted sum
__device__ __align__(16) float g_cl3T[(size_t)BB * L3 * C3];  // [b][pix][c]
__device__ __align__(16) float g_cl2T[(size_t)BB * L2n * C2];
__device__ __align__(16) float g_cl1T[(size_t)BB * L1n * C1];
__device__ float g_sq[2][BB * L3];                    // per-pixel sq-norm: 0=img 1=ref
__device__ __align__(16) float g_nrm[2][BB * L3];     // 0: nq(img) norm, 1: 1/nk(ref)
__device__ int   g_idx[BB * L3];                      // argmax index per query
__device__ __align__(16) float g_zero[16];            // stays zero (never written)

// ---------------- helpers -----------------------------------------------------
__device__ __forceinline__ void cp_async16(uint32_t smem, const void* gmem) {
    asm volatile("cp.async.cg.shared.global [%0], [%1], 16;\n" :: "r"(smem), "l"(gmem));
}
__device__ __forceinline__ void cp_commit() {
    asm volatile("cp.async.commit_group;\n" ::: "memory");
}
__device__ __forceinline__ void cp_wait0() {
    asm volatile("cp.async.wait_group 0;\n" ::: "memory");
}
// packed fp32x2 FMA: d = a*b + d  (componentwise, exact fp32 semantics)
__device__ __forceinline__ void fma2(unsigned long long& d, unsigned long long a,
                                     unsigned long long b) {
    asm("fma.rn.f32x2 %0, %1, %2, %0;" : "+l"(d) : "l"(a), "l"(b));
}
__device__ __forceinline__ unsigned long long bcast2(float x) {
    unsigned long long r;
    asm("mov.b64 %0, {%1, %1};" : "=l"(r) : "f"(x));
    return r;
}

// ---------------- 1) per-pixel squared norms ---------------------------------
__global__ void sqsum_kernel(const float* __restrict__ img, const float* __restrict__ ref) {
    int l = blockIdx.x * 256 + threadIdx.x;           // 0..2303
    int b = blockIdx.y;
    int which = blockIdx.z;                           // 0=img 1=ref
    const float* src = (which == 0) ? img : ref;
    src += (size_t)b * C3 * L3 + l;
    float s = 0.f;
    #pragma unroll 4
    for (int c = 0; c < C3; c++) {
        float v = src[(size_t)c * L3];
        s += v * v;
    }
    g_sq[which][b * L3 + l] = s;
}

// ---------------- 2) 3x3 box-sum -> patch norm -------------------------------
__global__ void boxnorm_kernel() {
    int l = blockIdx.x * 256 + threadIdx.x;
    int b = blockIdx.y;
    int which = blockIdx.z;
    int y = l / H3, x = l % H3;
    const float* s = &g_sq[which][b * L3];
    float acc = 0.f;
    #pragma unroll
    for (int dy = -1; dy <= 1; dy++) {
        int yy = y + dy;
        if ((unsigned)yy >= H3) continue;
        #pragma unroll
        for (int dx = -1; dx <= 1; dx++) {
            int xx = x + dx;
            if ((unsigned)xx >= H3) continue;
            acc += s[yy * H3 + xx];
        }
    }
    float n = fmaxf(sqrtf(acc), EPSN);
    g_nrm[which][b * L3 + l] = (which == 1) ? (1.0f / n) : n;
}

// ---------------- 3) transpose cl_ref to channel-last ------------------------
__global__ void transpose_kernel(const float* __restrict__ src, int C, int L, int sel) {
    float* dst = (sel == 0) ? g_cl3T : (sel == 1) ? g_cl2T : g_cl1T;
    __shared__ float tile[32][33];
    int l0 = blockIdx.x * 32, c0 = blockIdx.y * 32, b = blockIdx.z;
    const float* s = src + (size_t)b * C * L;
    float* d = dst + (size_t)b * L * C;
    #pragma unroll
    for (int i = threadIdx.y; i < 32; i += 8)
        tile[i][threadIdx.x] = s[(size_t)(c0 + i) * L + l0 + threadIdx.x];
    __syncthreads();
    #pragma unroll
    for (int i = threadIdx.y; i < 32; i += 8)
        d[(size_t)(l0 + i) * C + c0 + threadIdx.x] = tile[threadIdx.x][i];
}

// ---------------- 4) SGEMM via packed FFMA2 (fma.rn.f32x2) -------------------
__global__ void __launch_bounds__(256, 2) gemm_kernel(const float* __restrict__ img,
                                                      const float* __restrict__ ref) {
    const int b  = blockIdx.z;
    const int m0 = blockIdx.y * 128;
    const int n0 = blockIdx.x * 128;
    const float* A  = img + (size_t)b * C3 * L3;   // [k][m]
    const float* Bm = ref + (size_t)b * C3 * L3;   // [k][n]
    float* Cc = g_P + (size_t)b * L3 * L3;

    __shared__ __align__(16) float As[2][BK][128];
    __shared__ __align__(16) float Bs[2][BK][128];

    const int tid = threadIdx.x;
    const int lr  = tid >> 5;
    const int lc  = (tid & 31) * 4;
    const int tx  = tid & 15;
    const int ty  = tid >> 4;

    const float* gA0 = &A [(size_t)lr       * L3 + m0 + lc];
    const float* gA1 = &A [(size_t)(lr + 8) * L3 + m0 + lc];
    const float* gB0 = &Bm[(size_t)lr       * L3 + n0 + lc];
    const float* gB1 = &Bm[(size_t)(lr + 8) * L3 + n0 + lc];
    const size_t kstep = (size_t)BK * L3;

    uint32_t sA0[2], sA1[2], sB0[2], sB1[2];
    #pragma unroll
    for (int u = 0; u < 2; u++) {
        sA0[u] = (uint32_t)__cvta_generic_to_shared(&As[u][lr][lc]);
        sA1[u] = (uint32_t)__cvta_generic_to_shared(&As[u][lr + 8][lc]);
        sB0[u] = (uint32_t)__cvta_generic_to_shared(&Bs[u][lr][lc]);
        sB1[u] = (uint32_t)__cvta_generic_to_shared(&Bs[u][lr + 8][lc]);
    }

    unsigned long long acc2[8][4];
    #pragma unroll
    for (int i = 0; i < 8; i++)
        #pragma unroll
        for (int j = 0; j < 4; j++) acc2[i][j] = 0ULL;

    cp_async16(sA0[0], gA0); cp_async16(sA1[0], gA1);
    cp_async16(sB0[0], gB0); cp_async16(sB1[0], gB1);
    cp_commit();

    int buf = 0;
    for (int k0 = 0; k0 < C3; k0 += BK) {
        cp_wait0();
        __syncthreads();

        if (k0 + BK < C3) {
            size_t off = (size_t)((k0 + BK) / BK) * kstep;
            int nb = buf ^ 1;
            cp_async16(sA0[nb], gA0 + off); cp_async16(sA1[nb], gA1 + off);
            cp_async16(sB0[nb], gB0 + off); cp_async16(sB1[nb], gB1 + off);
            cp_commit();
        }

        #pragma unroll
        for (int kk = 0; kk < BK; kk++) {
            float a[8];
            unsigned long long b2[4];
            *(float4*)&a[0] = *(float4*)&As[buf][kk][ty * 4];
            *(float4*)&a[4] = *(float4*)&As[buf][kk][64 + ty * 4];
            {
                const unsigned long long* p0 =
                    (const unsigned long long*)&Bs[buf][kk][tx * 4];
                const unsigned long long* p1 =
                    (const unsigned long long*)&Bs[buf][kk][64 + tx * 4];
                b2[0] = p0[0]; b2[1] = p0[1];
                b2[2] = p1[0]; b2[3] = p1[1];
            }
            #pragma unroll
            for (int i = 0; i < 8; i++) {
                unsigned long long a2 = bcast2(a[i]);
                fma2(acc2[i][0], a2, b2[0]);
                fma2(acc2[i][1], a2, b2[1]);
                fma2(acc2[i][2], a2, b2[2]);
                fma2(acc2[i][3], a2, b2[3]);
            }
        }
        buf ^= 1;
    }

    #pragma unroll
    for (int i = 0; i < 8; i++) {
        int m = m0 + ((i < 4) ? (ty * 4 + i) : (64 + ty * 4 + i - 4));
        float* row = Cc + (size_t)m * L3;
        *(unsigned long long*)&row[n0 + tx * 4]          = acc2[i][0];
        *(unsigned long long*)&row[n0 + tx * 4 + 2]      = acc2[i][1];
        *(unsigned long long*)&row[n0 + 64 + tx * 4]     = acc2[i][2];
        *(unsigned long long*)&row[n0 + 64 + tx * 4 + 2] = acc2[i][3];
    }
}

// ---------------- 5a) x-pass: G[r][c] = Pm1[c-1] + P[c] + Pp1[c+1] -----------
// x-validity masks applied by zeroing boundary entries in smem.
__global__ void gpass1_kernel() {
    __shared__ __align__(16) float sA[2312];   // A[j] at sA[j+4]
    __shared__ __align__(16) float sB[2304];   // B[j] at sB[j]
    __shared__ __align__(16) float sC[2312];   // C[j] at sC[j]
    int r = blockIdx.x, b = blockIdx.y;
    int xq = r % H3;
    const float* Pb = g_P + (size_t)b * L3 * L3;
    float* Gb = g_G + (size_t)b * L3 * L3;
    int tid = threadIdx.x;

    const float4* rowA = (const float4*)(Pb + (size_t)(r - 1) * L3);
    const float4* rowB = (const float4*)(Pb + (size_t)r * L3);
    const float4* rowC = (const float4*)(Pb + (size_t)(r + 1) * L3);
    bool va = (xq >= 1), vc = (xq <= H3 - 2);
    float4 z4 = make_float4(0.f, 0.f, 0.f, 0.f);
    for (int i = tid; i < 576; i += 256) {
        *(float4*)&sB[i * 4]     = rowB[i];
        *(float4*)&sA[4 + i * 4] = va ? rowA[i] : z4;
        *(float4*)&sC[i * 4]     = vc ? rowC[i] : z4;
    }
    __syncthreads();
    // boundary masking: A entries at j%48==47 (incl j=-1), C entries at j%48==0
    if (tid < 48) {
        sA[4 + 47 + tid * 48] = 0.f;     // j = 47 + 48*tid
        sC[tid * 48] = 0.f;              // j = 48*tid
    }
    if (tid == 48) { sA[3] = 0.f; sC[2304] = 0.f; sC[2305] = 0.f; sC[2306] = 0.f; sC[2307] = 0.f; }
    __syncthreads();

    float* gr = Gb + (size_t)r * L3;
    for (int i = tid; i < 576; i += 256) {
        int c = i * 4;
        float4 o;
        o.x = sA[3 + c]     + sB[c]     + sC[c + 1];
        o.y = sA[3 + c + 1] + sB[c + 1] + sC[c + 2];
        o.z = sA[3 + c + 2] + sB[c + 2] + sC[c + 3];
        o.w = sA[3 + c + 3] + sB[c + 3] + sC[c + 4];
        *(float4*)&gr[c] = o;
    }
}

// ---------------- 5b) y-pass + max/argmax: S = sum_di G[lq+48di][lk+48di] ----
__global__ void maxarg_kernel(float* __restrict__ outS) {
    int b = blockIdx.y, lq = blockIdx.x;
    int yq = lq / H3;
    const float4* Gb4 = (const float4*)(g_G + (size_t)b * L3 * L3);
    const float4* z4p = (const float4*)g_zero;

    // per-band row bases (in float4 units): Gb4 + (lq+48di)*576 + 12di
    const float4* rb[3];
    bool qv[3];
    #pragma unroll
    for (int t = 0; t < 3; t++) {
        int di = t - 1;
        qv[t] = ((unsigned)(yq + di) < H3);
        rb[t] = qv[t] ? (Gb4 + (size_t)(lq + 48 * di) * 576 + 12 * di) : z4p;
    }
    const float4* rnk4 = (const float4*)&g_nrm[1][b * L3];

    float best = -1e30f; int bi = 0;
    for (int gi = threadIdx.x; gi < 576; gi += 256) {
        int yk = gi / 12;                        // lk = gi*4, yk = lk/48
        bool k0 = qv[0] && (yk >= 1);
        bool k2 = qv[2] && (yk <= H3 - 2);
        float4 v0 = k0 ? rb[0][gi] : *z4p;
        float4 v1 = qv[1] ? rb[1][gi] : *z4p;
        float4 v2 = k2 ? rb[2][gi] : *z4p;
        float4 rk = rnk4[gi];
        float s0 = (v0.x + v1.x + v2.x) * rk.x;
        float s1 = (v0.y + v1.y + v2.y) * rk.y;
        float s2 = (v0.z + v1.z + v2.z) * rk.z;
        float s3 = (v0.w + v1.w + v2.w) * rk.w;
        int lk = gi * 4;
        if (s0 > best) { best = s0; bi = lk; }
        if (s1 > best) { best = s1; bi = lk + 1; }
        if (s2 > best) { best = s2; bi = lk + 2; }
        if (s3 > best) { best = s3; bi = lk + 3; }
    }

    __shared__ float sv[256];
    __shared__ int   si[256];
    sv[threadIdx.x] = best; si[threadIdx.x] = bi;
    __syncthreads();
    for (int st = 128; st > 0; st >>= 1) {
        if (threadIdx.x < st) {
            float o = sv[threadIdx.x + st]; int oi = si[threadIdx.x + st];
            if (o > sv[threadIdx.x] || (o == sv[threadIdx.x] && oi < si[threadIdx.x])) {
                sv[threadIdx.x] = o; si[threadIdx.x] = oi;
            }
        }
        __syncthreads();
    }
    if (threadIdx.x == 0) {
        g_idx[b * L3 + lq] = si[0];
        outS[b * L3 + lq]  = sv[0] / g_nrm[0][b * L3 + lq];
    }
}

// ---------------- 6) fused gather + fold-normalize (precomputed cell table) --
// grid = (W, BB, 4); block covers xpc=W/4 pixels of row y; 12 query cells/block.
__global__ void transfer_kernel(float* __restrict__ out, int C, int W, int ls, int sel,
                                int xpc) {
    const float* clT = (sel == 0) ? g_cl3T : (sel == 1) ? g_cl2T : g_cl1T;
    __shared__ __align__(16) float acc[3456];    // xpc*(C+8) <= 3456 floats
    __shared__ __align__(16) int4 ent[3][14];    // {dxs, base4, ok, pad}
    __shared__ float sinv[12];
    int b = blockIdx.y, y = blockIdx.x;
    int xlo = blockIdx.z * xpc;
    int tid = threadIdx.x;
    int cpg  = C >> 2;                           // threads per pixel
    int cg   = tid & (cpg - 1);
    int xsub = tid / cpg;
    int ppp  = 256 / cpg;
    int astr = C + 8;

    int tyq  = y >> ls;
    int txq0 = xlo >> ls;
    const int* idxb = g_idx + b * L3;

    // precompute query-cell table
    if (tid < 42) {
        int a = tid / 14, xi = tid % 14;
        int xq = txq0 - 1 + xi;
        int yq = tyq - 1 + a;
        int dxs = 0, base4 = 0, ok = 0;
        if ((unsigned)xq < H3 && (unsigned)yq < H3) {
            int idx = idxb[yq * H3 + xq];
            int yk = idx / H3, xk = idx % H3;
            int ys = y + ((yk - yq) << ls);
            if ((unsigned)ys < (unsigned)W) {
                ok = 1;
                base4 = ys * W * (C >> 2);
            }
            dxs = (xk - xq) << ls;
        }
        ent[a][xi] = make_int4(dxs, base4, ok, 0);
    }
    if (tid < 12) {
        int txq = txq0 + tid;
        int nvx = 1 + (txq > 0) + (txq < H3 - 1);
        int nvy = 1 + (tyq > 0) + (tyq < H3 - 1);
        sinv[tid] = 1.0f / (float)(nvx * nvy);
    }
    __syncthreads();

    const float4* f4b = (const float4*)(clT + (size_t)b * W * W * C);

    for (int xo = 0; xo < xpc; xo += ppp) {
        int x = xlo + xo + xsub;
        int xib = (x >> ls) - txq0;              // 0..11
        float4 sum = make_float4(0.f, 0.f, 0.f, 0.f);
        #pragma unroll
        for (int a = 0; a < 3; a++) {
            #pragma unroll
            for (int dx = 0; dx < 3; dx++) {
                int4 e = ent[a][xib + dx];
                int xs = x + e.x;
                if (e.z && (unsigned)xs < (unsigned)W) {
                    float4 v = f4b[e.y + xs * cpg + cg];
                    sum.x += v.x; sum.y += v.y; sum.z += v.z; sum.w += v.w;
                }
            }
        }
        float ic = sinv[xib];
        *(float4*)&acc[(xo + xsub) * astr + cg * 4] =
            make_float4(sum.x * ic, sum.y * ic, sum.z * ic, sum.w * ic);
    }
    __syncthreads();

    size_t ob = (size_t)b * C * W * W + (size_t)y * W + xlo;
    int tot = C * xpc;                           // == 3072 for all levels
    for (int i = tid; i < tot; i += 256) {
        int c = i / xpc, x = i % xpc;
        out[ob + (size_t)c * W * W + x] = acc[x * astr + c];
    }
}

// ---------------- launch ------------------------------------------------------
extern "C" void kernel_launch(void* const* d_in, const int* in_sizes, int n_in,
                              void* d_out, int out_size) {
    const float* img = (const float*)d_in[0];   // dh_img_lv3 [4,256,48,48]
    const float* ref = (const float*)d_in[1];   // dh_ref_lv3 [4,256,48,48]
    const float* cl1 = (const float*)d_in[2];   // cl_ref_lv1 [4,64,192,192]
    const float* cl2 = (const float*)d_in[3];   // cl_ref_lv2 [4,128,96,96]
    const float* cl3 = (const float*)d_in[4];   // cl_ref_lv3 [4,256,48,48]

    float* outS  = (float*)d_out;               // [4,1,48,48]
    float* outT3 = outS  + BB * L3;             // [4,256,48,48]
    float* outT2 = outT3 + (size_t)BB * C3 * L3;    // [4,128,96,96]
    float* outT1 = outT2 + (size_t)BB * C2 * L2n;   // [4,64,192,192]

    gemm_kernel<<<dim3(L3 / 128, L3 / 128, BB), 256>>>(img, ref);                     // 0
    sqsum_kernel  <<<dim3(9, BB, 2), 256>>>(img, ref);                                // 1
    boxnorm_kernel<<<dim3(9, BB, 2), 256>>>();                                        // 2

    gpass1_kernel<<<dim3(L3, BB), 256>>>();                                           // 3 (profiled)
    maxarg_kernel<<<dim3(L3, BB), 256>>>(outS);                                       // 4

    transpose_kernel<<<dim3(L3  / 32, C3 / 32, BB), dim3(32, 8)>>>(cl3, C3, L3,  0);  // 5
    transpose_kernel<<<dim3(L2n / 32, C2 / 32, BB), dim3(32, 8)>>>(cl2, C2, L2n, 1);  // 6
    transpose_kernel<<<dim3(L1n / 32, C1 / 32, BB), dim3(32, 8)>>>(cl1, C1, L1n, 2);  // 7

    transfer_kernel<<<dim3(H3, BB, 4), 256>>>(outT3, C3, H3, 0, 0, H3 / 4);           // 8
    transfer_kernel<<<dim3(H2, BB, 4), 256>>>(outT2, C2, H2, 1, 1, H2 / 4);           // 9
    transfer_kernel<<<dim3(H1, BB, 4), 256>>>(outT1, C1, H1, 2, 2, H1 / 4);           // 10
}

// round 10
// speedup vs baseline: 2.2339x; 1.0030x over previous
#include <cuda_runtime.h>
#include <cstdint>

// Problem constants
#define BB   4
#define C3   256
#define H3   48
#define L3   (H3*H3)          // 2304
#define C2   128
#define H2   96
#define L2n  (H2*H2)          // 9216
#define C1   64
#define H1   192
#define L1n  (H1*H1)          // 36864
#define EPSN 1e-12f

#define BK2 32
#define GEMM_SMEM (2 * BK2 * 128 * 2 * 4)      // 65536 bytes

// ---------------- scratch (static device globals; no allocation) -------------
__device__ __align__(16) float g_P[(size_t)BB * L3 * L3];   // [b][lq][lk]  ~85MB
__device__ __align__(16) float g_G[(size_t)BB * L3 * L3];   // x-pass of shifted sum
__device__ __align__(16) float g_cl3T[(size_t)BB * L3 * C3];  // [b][pix][c]
__device__ __align__(16) float g_cl2T[(size_t)BB * L2n * C2];
__device__ __align__(16) float g_cl1T[(size_t)BB * L1n * C1];
__device__ float g_sq[2][BB * L3];                    // per-pixel sq-norm: 0=img 1=ref
__device__ __align__(16) float g_nrm[2][BB * L3];     // 0: nq(img) norm, 1: 1/nk(ref)
__device__ int   g_idx[BB * L3];                      // argmax index per query
__device__ __align__(16) float g_zero[16];            // stays zero (never written)

// ---------------- helpers -----------------------------------------------------
__device__ __forceinline__ void cp_async16(uint32_t smem, const void* gmem) {
    asm volatile("cp.async.cg.shared.global [%0], [%1], 16;\n" :: "r"(smem), "l"(gmem));
}
__device__ __forceinline__ void cp_commit() {
    asm volatile("cp.async.commit_group;\n" ::: "memory");
}
__device__ __forceinline__ void cp_wait0() {
    asm volatile("cp.async.wait_group 0;\n" ::: "memory");
}
// packed fp32x2 FMA: d = a*b + d  (componentwise, exact fp32 semantics)
__device__ __forceinline__ void fma2(unsigned long long& d, unsigned long long a,
                                     unsigned long long b) {
    asm("fma.rn.f32x2 %0, %1, %2, %0;" : "+l"(d) : "l"(a), "l"(b));
}
__device__ __forceinline__ unsigned long long bcast2(float x) {
    unsigned long long r;
    asm("mov.b64 %0, {%1, %1};" : "=l"(r) : "f"(x));
    return r;
}

// ---------------- 1) per-pixel squared norms ---------------------------------
__global__ void sqsum_kernel(const float* __restrict__ img, const float* __restrict__ ref) {
    int l = blockIdx.x * 256 + threadIdx.x;           // 0..2303
    int b = blockIdx.y;
    int which = blockIdx.z;                           // 0=img 1=ref
    const float* src = (which == 0) ? img : ref;
    src += (size_t)b * C3 * L3 + l;
    float s = 0.f;
    #pragma unroll 4
    for (int c = 0; c < C3; c++) {
        float v = src[(size_t)c * L3];
        s += v * v;
    }
    g_sq[which][b * L3 + l] = s;
}

// ---------------- 2) 3x3 box-sum -> patch norm -------------------------------
__global__ void boxnorm_kernel() {
    int l = blockIdx.x * 256 + threadIdx.x;
    int b = blockIdx.y;
    int which = blockIdx.z;
    int y = l / H3, x = l % H3;
    const float* s = &g_sq[which][b * L3];
    float acc = 0.f;
    #pragma unroll
    for (int dy = -1; dy <= 1; dy++) {
        int yy = y + dy;
        if ((unsigned)yy >= H3) continue;
        #pragma unroll
        for (int dx = -1; dx <= 1; dx++) {
            int xx = x + dx;
            if ((unsigned)xx >= H3) continue;
            acc += s[yy * H3 + xx];
        }
    }
    float n = fmaxf(sqrtf(acc), EPSN);
    g_nrm[which][b * L3 + l] = (which == 1) ? (1.0f / n) : n;
}

// ---------------- 3) transpose cl_ref to channel-last ------------------------
__global__ void transpose_kernel(const float* __restrict__ src, int C, int L, int sel) {
    float* dst = (sel == 0) ? g_cl3T : (sel == 1) ? g_cl2T : g_cl1T;
    __shared__ float tile[32][33];
    int l0 = blockIdx.x * 32, c0 = blockIdx.y * 32, b = blockIdx.z;
    const float* s = src + (size_t)b * C * L;
    float* d = dst + (size_t)b * L * C;
    #pragma unroll
    for (int i = threadIdx.y; i < 32; i += 8)
        tile[i][threadIdx.x] = s[(size_t)(c0 + i) * L + l0 + threadIdx.x];
    __syncthreads();
    #pragma unroll
    for (int i = threadIdx.y; i < 32; i += 8)
        d[(size_t)(l0 + i) * C + c0 + threadIdx.x] = tile[threadIdx.x][i];
}

// ---------------- 4) SGEMM via packed FFMA2, BK=32, dynamic smem -------------
__global__ void __launch_bounds__(256, 2) gemm_kernel(const float* __restrict__ img,
                                                      const float* __restrict__ ref) {
    extern __shared__ __align__(16) float sm[];
    // layout: As[2][32][128] at 0, Bs[2][32][128] at 8192 floats
    const int b  = blockIdx.z;
    const int m0 = blockIdx.y * 128;
    const int n0 = blockIdx.x * 128;
    const float* A  = img + (size_t)b * C3 * L3;   // [k][m]
    const float* Bm = ref + (size_t)b * C3 * L3;   // [k][n]
    float* Cc = g_P + (size_t)b * L3 * L3;

    const int tid = threadIdx.x;
    const int lr  = tid >> 5;            // 0..7
    const int lc  = (tid & 31) * 4;
    const int tx  = tid & 15;
    const int ty  = tid >> 4;

    // global srcs: rows lr+8i, i=0..3 per matrix
    const float* gA[4]; const float* gB[4];
    uint32_t sA[2][4], sB[2][4];
    #pragma unroll
    for (int i = 0; i < 4; i++) {
        gA[i] = &A [(size_t)(lr + 8 * i) * L3 + m0 + lc];
        gB[i] = &Bm[(size_t)(lr + 8 * i) * L3 + n0 + lc];
        #pragma unroll
        for (int u = 0; u < 2; u++) {
            sA[u][i] = (uint32_t)__cvta_generic_to_shared(
                &sm[u * 4096 + (lr + 8 * i) * 128 + lc]);
            sB[u][i] = (uint32_t)__cvta_generic_to_shared(
                &sm[8192 + u * 4096 + (lr + 8 * i) * 128 + lc]);
        }
    }
    const size_t kstep = (size_t)BK2 * L3;

    unsigned long long acc2[8][4];
    #pragma unroll
    for (int i = 0; i < 8; i++)
        #pragma unroll
        for (int j = 0; j < 4; j++) acc2[i][j] = 0ULL;

    #pragma unroll
    for (int i = 0; i < 4; i++) { cp_async16(sA[0][i], gA[i]); cp_async16(sB[0][i], gB[i]); }
    cp_commit();

    int buf = 0;
    for (int ks = 0; ks < C3 / BK2; ks++) {
        cp_wait0();
        __syncthreads();

        if (ks + 1 < C3 / BK2) {
            size_t off = (size_t)(ks + 1) * kstep;
            int nb = buf ^ 1;
            #pragma unroll
            for (int i = 0; i < 4; i++) {
                cp_async16(sA[nb][i], gA[i] + off);
                cp_async16(sB[nb][i], gB[i] + off);
            }
            cp_commit();
        }

        const float* Ab = &sm[buf * 4096];
        const float* Bb = &sm[8192 + buf * 4096];
        #pragma unroll
        for (int kk = 0; kk < BK2; kk++) {
            float a[8];
            *(float4*)&a[0] = *(const float4*)&Ab[kk * 128 + ty * 4];
            *(float4*)&a[4] = *(const float4*)&Ab[kk * 128 + 64 + ty * 4];
            float4 bv0 = *(const float4*)&Bb[kk * 128 + tx * 4];
            float4 bv1 = *(const float4*)&Bb[kk * 128 + 64 + tx * 4];
            unsigned long long b2[4];
            b2[0] = ((unsigned long long*)&bv0)[0];
            b2[1] = ((unsigned long long*)&bv0)[1];
            b2[2] = ((unsigned long long*)&bv1)[0];
            b2[3] = ((unsigned long long*)&bv1)[1];
            #pragma unroll
            for (int i = 0; i < 8; i++) {
                unsigned long long a2 = bcast2(a[i]);
                fma2(acc2[i][0], a2, b2[0]);
                fma2(acc2[i][1], a2, b2[1]);
                fma2(acc2[i][2], a2, b2[2]);
                fma2(acc2[i][3], a2, b2[3]);
            }
        }
        buf ^= 1;
    }

    #pragma unroll
    for (int i = 0; i < 8; i++) {
        int m = m0 + ((i < 4) ? (ty * 4 + i) : (64 + ty * 4 + i - 4));
        float* row = Cc + (size_t)m * L3;
        *(unsigned long long*)&row[n0 + tx * 4]          = acc2[i][0];
        *(unsigned long long*)&row[n0 + tx * 4 + 2]      = acc2[i][1];
        *(unsigned long long*)&row[n0 + 64 + tx * 4]     = acc2[i][2];
        *(unsigned long long*)&row[n0 + 64 + tx * 4 + 2] = acc2[i][3];
    }
}

// ---------------- 5a) x-pass: G[r][c] = A[c-1] + B[c] + C[c+1], 4 rows/block -
// Raw 6-row smem load; boundary masks are two per-group predicates; row-level
// xq==0/47 handled by uniform branches.
#define SRS 2312
__global__ void gpass1_kernel() {
    __shared__ __align__(16) float sR[6 * SRS];   // row i data at sR[i*SRS + 4 + j]
    int r0 = blockIdx.x * 4, b = blockIdx.y;
    const float* Pb = g_P + (size_t)b * L3 * L3;
    float* Gb = g_G + (size_t)b * L3 * L3;
    int tid = threadIdx.x;

    #pragma unroll
    for (int i = 0; i < 6; i++) {
        int rr = min(max(r0 - 1 + i, 0), L3 - 1);   // clamped rows never used
        const float4* src = (const float4*)(Pb + (size_t)rr * L3);
        float4* dst = (float4*)&sR[i * SRS + 4];
        for (int g = tid; g < 576; g += 256) dst[g] = src[g];
    }
    __syncthreads();

    #pragma unroll
    for (int j = 0; j < 4; j++) {
        int r = r0 + j;
        int xq = r % H3;
        const float* Aj = &sR[j * SRS + 4];
        const float* Bj = &sR[(j + 1) * SRS + 4];
        const float* Cj = &sR[(j + 2) * SRS + 4];
        float* gr = Gb + (size_t)r * L3;
        bool hasA = (xq != 0), hasC = (xq != H3 - 1);

        if (hasA && hasC) {
            for (int g = tid; g < 576; g += 256) {
                int c = g * 4;
                int m = (g % 12) * 4;
                float4 bv = *(const float4*)&Bj[c];
                float a0 = (m != 0) ? Aj[c - 1] : 0.f;
                float c3 = (m != 44) ? Cj[c + 4] : 0.f;
                float4 o;
                o.x = a0        + bv.x + Cj[c + 1];
                o.y = Aj[c]     + bv.y + Cj[c + 2];
                o.z = Aj[c + 1] + bv.z + Cj[c + 3];
                o.w = Aj[c + 2] + bv.w + c3;
                *(float4*)&gr[c] = o;
            }
        } else if (!hasA) {
            for (int g = tid; g < 576; g += 256) {
                int c = g * 4;
                int m = (g % 12) * 4;
                float4 bv = *(const float4*)&Bj[c];
                float c3 = (m != 44) ? Cj[c + 4] : 0.f;
                float4 o;
                o.x = bv.x + Cj[c + 1];
                o.y = bv.y + Cj[c + 2];
                o.z = bv.z + Cj[c + 3];
                o.w = bv.w + c3;
                *(float4*)&gr[c] = o;
            }
        } else {
            for (int g = tid; g < 576; g += 256) {
                int c = g * 4;
                int m = (g % 12) * 4;
                float4 bv = *(const float4*)&Bj[c];
                float a0 = (m != 0) ? Aj[c - 1] : 0.f;
                float4 o;
                o.x = a0        + bv.x;
                o.y = Aj[c]     + bv.y;
                o.z = Aj[c + 1] + bv.z;
                o.w = Aj[c + 2] + bv.w;
                *(float4*)&gr[c] = o;
            }
        }
    }
}

// ---------------- 5b) y-pass + max/argmax: S = sum_di G[lq+48di][lk+48di] ----
__global__ void maxarg_kernel(float* __restrict__ outS) {
    int b = blockIdx.y, lq = blockIdx.x;
    int yq = lq / H3;
    const float4* Gb4 = (const float4*)(g_G + (size_t)b * L3 * L3);
    const float4* z4p = (const float4*)g_zero;

    const float4* rb[3];
    bool qv[3];
    #pragma unroll
    for (int t = 0; t < 3; t++) {
        int di = t - 1;
        qv[t] = ((unsigned)(yq + di) < H3);
        rb[t] = qv[t] ? (Gb4 + (size_t)(lq + 48 * di) * 576 + 12 * di) : z4p;
    }
    const float4* rnk4 = (const float4*)&g_nrm[1][b * L3];

    float best = -1e30f; int bi = 0;
    for (int gi = threadIdx.x; gi < 576; gi += 256) {
        int yk = gi / 12;
        bool k0 = qv[0] && (yk >= 1);
        bool k2 = qv[2] && (yk <= H3 - 2);
        float4 v0 = k0 ? rb[0][gi] : *z4p;
        float4 v1 = qv[1] ? rb[1][gi] : *z4p;
        float4 v2 = k2 ? rb[2][gi] : *z4p;
        float4 rk = rnk4[gi];
        float s0 = (v0.x + v1.x + v2.x) * rk.x;
        float s1 = (v0.y + v1.y + v2.y) * rk.y;
        float s2 = (v0.z + v1.z + v2.z) * rk.z;
        float s3 = (v0.w + v1.w + v2.w) * rk.w;
        int lk = gi * 4;
        if (s0 > best) { best = s0; bi = lk; }
        if (s1 > best) { best = s1; bi = lk + 1; }
        if (s2 > best) { best = s2; bi = lk + 2; }
        if (s3 > best) { best = s3; bi = lk + 3; }
    }

    __shared__ float sv[256];
    __shared__ int   si[256];
    sv[threadIdx.x] = best; si[threadIdx.x] = bi;
    __syncthreads();
    for (int st = 128; st > 0; st >>= 1) {
        if (threadIdx.x < st) {
            float o = sv[threadIdx.x + st]; int oi = si[threadIdx.x + st];
            if (o > sv[threadIdx.x] || (o == sv[threadIdx.x] && oi < si[threadIdx.x])) {
                sv[threadIdx.x] = o; si[threadIdx.x] = oi;
            }
        }
        __syncthreads();
    }
    if (threadIdx.x == 0) {
        g_idx[b * L3 + lq] = si[0];
        outS[b * L3 + lq]  = sv[0] / g_nrm[0][b * L3 + lq];
    }
}

// ---------------- 6) fused gather + fold-normalize (precomputed cell table) --
__global__ void transfer_kernel(float* __restrict__ out, int C, int W, int ls, int sel,
                                int xpc) {
    const float* clT = (sel == 0) ? g_cl3T : (sel == 1) ? g_cl2T : g_cl1T;
    __shared__ __align__(16) float acc[3456];    // xpc*(C+8) <= 3456 floats
    __shared__ __align__(16) int4 ent[3][14];    // {dxs, base4, ok, pad}
    __shared__ float sinv[12];
    int b = blockIdx.y, y = blockIdx.x;
    int xlo = blockIdx.z * xpc;
    int tid = threadIdx.x;
    int cpg  = C >> 2;
    int cg   = tid & (cpg - 1);
    int xsub = tid / cpg;
    int ppp  = 256 / cpg;
    int astr = C + 8;

    int tyq  = y >> ls;
    int txq0 = xlo >> ls;
    const int* idxb = g_idx + b * L3;

    if (tid < 42) {
        int a = tid / 14, xi = tid % 14;
        int xq = txq0 - 1 + xi;
        int yq = tyq - 1 + a;
        int dxs = 0, base4 = 0, ok = 0;
        if ((unsigned)xq < H3 && (unsigned)yq < H3) {
            int idx = idxb[yq * H3 + xq];
            int yk = idx / H3, xk = idx % H3;
            int ys = y + ((yk - yq) << ls);
            if ((unsigned)ys < (unsigned)W) {
                ok = 1;
                base4 = ys * W * (C >> 2);
            }
            dxs = (xk - xq) << ls;
        }
        ent[a][xi] = make_int4(dxs, base4, ok, 0);
    }
    if (tid < 12) {
        int txq = txq0 + tid;
        int nvx = 1 + (txq > 0) + (txq < H3 - 1);
        int nvy = 1 + (tyq > 0) + (tyq < H3 - 1);
        sinv[tid] = 1.0f / (float)(nvx * nvy);
    }
    __syncthreads();

    const float4* f4b = (const float4*)(clT + (size_t)b * W * W * C);

    for (int xo = 0; xo < xpc; xo += ppp) {
        int x = xlo + xo + xsub;
        int xib = (x >> ls) - txq0;
        float4 sum = make_float4(0.f, 0.f, 0.f, 0.f);
        #pragma unroll
        for (int a = 0; a < 3; a++) {
            #pragma unroll
            for (int dx = 0; dx < 3; dx++) {
                int4 e = ent[a][xib + dx];
                int xs = x + e.x;
                if (e.z && (unsigned)xs < (unsigned)W) {
                    float4 v = f4b[e.y + xs * cpg + cg];
                    sum.x += v.x; sum.y += v.y; sum.z += v.z; sum.w += v.w;
                }
            }
        }
        float ic = sinv[xib];
        *(float4*)&acc[(xo + xsub) * astr + cg * 4] =
            make_float4(sum.x * ic, sum.y * ic, sum.z * ic, sum.w * ic);
    }
    __syncthreads();

    size_t ob = (size_t)b * C * W * W + (size_t)y * W + xlo;
    int tot = C * xpc;
    for (int i = tid; i < tot; i += 256) {
        int c = i / xpc, x = i % xpc;
        out[ob + (size_t)c * W * W + x] = acc[x * astr + c];
    }
}

// ---------------- launch ------------------------------------------------------
extern "C" void kernel_launch(void* const* d_in, const int* in_sizes, int n_in,
                              void* d_out, int out_size) {
    const float* img = (const float*)d_in[0];   // dh_img_lv3 [4,256,48,48]
    const float* ref = (const float*)d_in[1];   // dh_ref_lv3 [4,256,48,48]
    const float* cl1 = (const float*)d_in[2];   // cl_ref_lv1 [4,64,192,192]
    const float* cl2 = (const float*)d_in[3];   // cl_ref_lv2 [4,128,96,96]
    const float* cl3 = (const float*)d_in[4];   // cl_ref_lv3 [4,256,48,48]

    float* outS  = (float*)d_out;               // [4,1,48,48]
    float* outT3 = outS  + BB * L3;             // [4,256,48,48]
    float* outT2 = outT3 + (size_t)BB * C3 * L3;    // [4,128,96,96]
    float* outT1 = outT2 + (size_t)BB * C2 * L2n;   // [4,64,192,192]

    cudaFuncSetAttribute(gemm_kernel,
                         cudaFuncAttributeMaxDynamicSharedMemorySize, GEMM_SMEM);

    sqsum_kernel  <<<dim3(9, BB, 2), 256>>>(img, ref);                                // 0
    boxnorm_kernel<<<dim3(9, BB, 2), 256>>>();                                        // 1
    transpose_kernel<<<dim3(L3  / 32, C3 / 32, BB), dim3(32, 8)>>>(cl3, C3, L3,  0);  // 2

    gemm_kernel<<<dim3(L3 / 128, L3 / 128, BB), 256, GEMM_SMEM>>>(img, ref);          // 3 (profiled)

    gpass1_kernel<<<dim3(L3 / 4, BB), 256>>>();                                       // 4
    maxarg_kernel<<<dim3(L3, BB), 256>>>(outS);                                       // 5

    transpose_kernel<<<dim3(L2n / 32, C2 / 32, BB), dim3(32, 8)>>>(cl2, C2, L2n, 1);  // 6
    transpose_kernel<<<dim3(L1n / 32, C1 / 32, BB), dim3(32, 8)>>>(cl1, C1, L1n, 2);  // 7

    transfer_kernel<<<dim3(H3, BB, 4), 256>>>(outT3, C3, H3, 0, 0, H3 / 4);           // 8
    transfer_kernel<<<dim3(H2, BB, 4), 256>>>(outT2, C2, H2, 1, 1, H2 / 4);           // 9
    transfer_kernel<<<dim3(H1, BB, 4), 256>>>(outT1, C1, H1, 2, 2, H1 / 4);           // 10
}

// round 11
// speedup vs baseline: 2.3507x; 1.0523x over previous
#include <cuda_runtime.h>
#include <cstdint>

// Problem constants
#define BB   4
#define C3   256
#define H3   48
#define L3   (H3*H3)          // 2304
#define C2   128
#define H2   96
#define L2n  (H2*H2)          // 9216
#define C1   64
#define H1   192
#define L1n  (H1*H1)          // 36864
#define EPSN 1e-12f

#define BK2 32
#define GEMM_SMEM (2 * BK2 * 128 * 2 * 4)      // 65536 bytes

// side_kernel block counts
#define NSQB 72                                 // 9 tiles x 2 tensors x 4 batches
#define NT3  2304
#define NT2  4608
#define NT1  9216
#define NSIDE (NSQB + NT3 + NT2 + NT1)          // 16200

// ---------------- scratch (static device globals; no allocation) -------------
__device__ __align__(16) float g_P[(size_t)BB * L3 * L3];   // [b][lq][lk]  ~85MB
__device__ __align__(16) float g_G[(size_t)BB * L3 * L3];   // x-pass of shifted sum
__device__ __align__(16) float g_cl3T[(size_t)BB * L3 * C3];  // [b][pix][c]
__device__ __align__(16) float g_cl2T[(size_t)BB * L2n * C2];
__device__ __align__(16) float g_cl1T[(size_t)BB * L1n * C1];
__device__ __align__(16) float g_nrm[2][BB * L3];     // 0: nq(img) norm, 1: 1/nk(ref)
__device__ int   g_idx[BB * L3];                      // argmax index per query
__device__ __align__(16) float g_zero[16];            // stays zero (never written)

// ---------------- helpers -----------------------------------------------------
__device__ __forceinline__ void cp_async16(uint32_t smem, const void* gmem) {
    asm volatile("cp.async.cg.shared.global [%0], [%1], 16;\n" :: "r"(smem), "l"(gmem));
}
__device__ __forceinline__ void cp_commit() {
    asm volatile("cp.async.commit_group;\n" ::: "memory");
}
__device__ __forceinline__ void cp_wait0() {
    asm volatile("cp.async.wait_group 0;\n" ::: "memory");
}
// packed fp32x2 FMA: d = a*b + d  (componentwise, exact fp32 semantics)
__device__ __forceinline__ void fma2(unsigned long long& d, unsigned long long a,
                                     unsigned long long b) {
    asm("fma.rn.f32x2 %0, %1, %2, %0;" : "+l"(d) : "l"(a), "l"(b));
}
__device__ __forceinline__ unsigned long long bcast2(float x) {
    unsigned long long r;
    asm("mov.b64 %0, {%1, %1};" : "=l"(r) : "f"(x));
    return r;
}

// ---------------- side kernel: 3 transposes + fused sqsum/boxnorm ------------
// Launched with PDL so its blocks fill gemm's wave gaps and tail.
__global__ void __launch_bounds__(256) side_kernel(const float* __restrict__ img,
                                                   const float* __restrict__ ref,
                                                   const float* __restrict__ cl1,
                                                   const float* __restrict__ cl2,
                                                   const float* __restrict__ cl3) {
    __shared__ float sbuf[1056];                 // transpose 32x33; sqsumbox uses 324
    int j = blockIdx.x;
    int tid = threadIdx.x;

    if (j < NSQB) {
        // ---- fused per-pixel sqnorm + 3x3 box-sum -> patch norm ----
        int tile = j % 9, which = (j / 9) & 1, b = j / 18;
        const float* src = ((which == 0) ? img : ref) + (size_t)b * C3 * L3;
        int ty0 = (tile / 3) * 16, tx0 = (tile % 3) * 16;
        for (int p = tid; p < 324; p += 256) {
            int py = ty0 + p / 18 - 1, px = tx0 + p % 18 - 1;
            float s = 0.f;
            if ((unsigned)py < H3 && (unsigned)px < H3) {
                const float* sp = src + py * H3 + px;
                #pragma unroll 4
                for (int c = 0; c < C3; c++) {
                    float v = sp[(size_t)c * L3];
                    s += v * v;
                }
            }
            sbuf[p] = s;
        }
        __syncthreads();
        {
            int py = tid / 16, px = tid % 16;       // all 256 threads
            float acc = 0.f;
            #pragma unroll
            for (int dy = 0; dy < 3; dy++)
                #pragma unroll
                for (int dx = 0; dx < 3; dx++)
                    acc += sbuf[(py + dy) * 18 + px + dx];
            float n = fmaxf(sqrtf(acc), EPSN);
            g_nrm[which][b * L3 + (ty0 + py) * H3 + tx0 + px] = which ? (1.0f / n) : n;
        }
        return;
    }

    // ---- transpose cl -> channel-last ----
    int q = j - NSQB;
    const float* src; float* dst; int C, L;
    if (q < NT3)            { src = cl3; dst = g_cl3T; C = C3; L = L3; }
    else if (q < NT3 + NT2) { q -= NT3;  src = cl2; dst = g_cl2T; C = C2; L = L2n; }
    else                    { q -= NT3 + NT2; src = cl1; dst = g_cl1T; C = C1; L = L1n; }
    int nl = L / 32, nc = C / 32;
    int l0 = (q % nl) * 32, c0 = ((q / nl) % nc) * 32, b = q / (nl * nc);
    const float* s = src + (size_t)b * C * L;
    float* d = dst + (size_t)b * L * C;
    int txx = tid % 32, tyy = tid / 32;
    #pragma unroll
    for (int i = tyy; i < 32; i += 8)
        sbuf[i * 33 + txx] = s[(size_t)(c0 + i) * L + l0 + txx];
    __syncthreads();
    #pragma unroll
    for (int i = tyy; i < 32; i += 8)
        d[(size_t)(l0 + i) * C + c0 + txx] = sbuf[txx * 33 + i];
}

// ---------------- 4) SGEMM via packed FFMA2, BK=32, dynamic smem -------------
__global__ void __launch_bounds__(256, 2) gemm_kernel(const float* __restrict__ img,
                                                      const float* __restrict__ ref) {
    // release PDL dependents immediately: side_kernel may co-schedule
    asm volatile("griddepcontrol.launch_dependents;" ::: "memory");

    extern __shared__ __align__(16) float sm[];
    const int b  = blockIdx.z;
    const int m0 = blockIdx.y * 128;
    const int n0 = blockIdx.x * 128;
    const float* A  = img + (size_t)b * C3 * L3;   // [k][m]
    const float* Bm = ref + (size_t)b * C3 * L3;   // [k][n]
    float* Cc = g_P + (size_t)b * L3 * L3;

    const int tid = threadIdx.x;
    const int lr  = tid >> 5;            // 0..7
    const int lc  = (tid & 31) * 4;
    const int tx  = tid & 15;
    const int ty  = tid >> 4;

    const float* gA[4]; const float* gB[4];
    uint32_t sA[2][4], sB[2][4];
    #pragma unroll
    for (int i = 0; i < 4; i++) {
        gA[i] = &A [(size_t)(lr + 8 * i) * L3 + m0 + lc];
        gB[i] = &Bm[(size_t)(lr + 8 * i) * L3 + n0 + lc];
        #pragma unroll
        for (int u = 0; u < 2; u++) {
            sA[u][i] = (uint32_t)__cvta_generic_to_shared(
                &sm[u * 4096 + (lr + 8 * i) * 128 + lc]);
            sB[u][i] = (uint32_t)__cvta_generic_to_shared(
                &sm[8192 + u * 4096 + (lr + 8 * i) * 128 + lc]);
        }
    }
    const size_t kstep = (size_t)BK2 * L3;

    unsigned long long acc2[8][4];
    #pragma unroll
    for (int i = 0; i < 8; i++)
        #pragma unroll
        for (int j = 0; j < 4; j++) acc2[i][j] = 0ULL;

    #pragma unroll
    for (int i = 0; i < 4; i++) { cp_async16(sA[0][i], gA[i]); cp_async16(sB[0][i], gB[i]); }
    cp_commit();

    int buf = 0;
    for (int ks = 0; ks < C3 / BK2; ks++) {
        cp_wait0();
        __syncthreads();

        if (ks + 1 < C3 / BK2) {
            size_t off = (size_t)(ks + 1) * kstep;
            int nb = buf ^ 1;
            #pragma unroll
            for (int i = 0; i < 4; i++) {
                cp_async16(sA[nb][i], gA[i] + off);
                cp_async16(sB[nb][i], gB[i] + off);
            }
            cp_commit();
        }

        const float* Ab = &sm[buf * 4096];
        const float* Bb = &sm[8192 + buf * 4096];
        #pragma unroll
        for (int kk = 0; kk < BK2; kk++) {
            float a[8];
            *(float4*)&a[0] = *(const float4*)&Ab[kk * 128 + ty * 4];
            *(float4*)&a[4] = *(const float4*)&Ab[kk * 128 + 64 + ty * 4];
            float4 bv0 = *(const float4*)&Bb[kk * 128 + tx * 4];
            float4 bv1 = *(const float4*)&Bb[kk * 128 + 64 + tx * 4];
            unsigned long long b2[4];
            b2[0] = ((unsigned long long*)&bv0)[0];
            b2[1] = ((unsigned long long*)&bv0)[1];
            b2[2] = ((unsigned long long*)&bv1)[0];
            b2[3] = ((unsigned long long*)&bv1)[1];
            #pragma unroll
            for (int i = 0; i < 8; i++) {
                unsigned long long a2 = bcast2(a[i]);
                fma2(acc2[i][0], a2, b2[0]);
                fma2(acc2[i][1], a2, b2[1]);
                fma2(acc2[i][2], a2, b2[2]);
                fma2(acc2[i][3], a2, b2[3]);
            }
        }
        buf ^= 1;
    }

    #pragma unroll
    for (int i = 0; i < 8; i++) {
        int m = m0 + ((i < 4) ? (ty * 4 + i) : (64 + ty * 4 + i - 4));
        float* row = Cc + (size_t)m * L3;
        *(unsigned long long*)&row[n0 + tx * 4]          = acc2[i][0];
        *(unsigned long long*)&row[n0 + tx * 4 + 2]      = acc2[i][1];
        *(unsigned long long*)&row[n0 + 64 + tx * 4]     = acc2[i][2];
        *(unsigned long long*)&row[n0 + 64 + tx * 4 + 2] = acc2[i][3];
    }
}

// ---------------- 5a) x-pass: G[r][c] = A[c-1] + B[c] + C[c+1], 4 rows/block -
#define SRS 2312
__global__ void gpass1_kernel() {
    __shared__ __align__(16) float sR[6 * SRS];
    int r0 = blockIdx.x * 4, b = blockIdx.y;
    const float* Pb = g_P + (size_t)b * L3 * L3;
    float* Gb = g_G + (size_t)b * L3 * L3;
    int tid = threadIdx.x;

    #pragma unroll
    for (int i = 0; i < 6; i++) {
        int rr = min(max(r0 - 1 + i, 0), L3 - 1);   // clamped rows never used
        const float4* src = (const float4*)(Pb + (size_t)rr * L3);
        float4* dst = (float4*)&sR[i * SRS + 4];
        for (int g = tid; g < 576; g += 256) dst[g] = src[g];
    }
    __syncthreads();

    #pragma unroll
    for (int j = 0; j < 4; j++) {
        int r = r0 + j;
        int xq = r % H3;
        const float* Aj = &sR[j * SRS + 4];
        const float* Bj = &sR[(j + 1) * SRS + 4];
        const float* Cj = &sR[(j + 2) * SRS + 4];
        float* gr = Gb + (size_t)r * L3;
        bool hasA = (xq != 0), hasC = (xq != H3 - 1);

        if (hasA && hasC) {
            for (int g = tid; g < 576; g += 256) {
                int c = g * 4;
                int m = (g % 12) * 4;
                float4 bv = *(const float4*)&Bj[c];
                float a0 = (m != 0) ? Aj[c - 1] : 0.f;
                float c3 = (m != 44) ? Cj[c + 4] : 0.f;
                float4 o;
                o.x = a0        + bv.x + Cj[c + 1];
                o.y = Aj[c]     + bv.y + Cj[c + 2];
                o.z = Aj[c + 1] + bv.z + Cj[c + 3];
                o.w = Aj[c + 2] + bv.w + c3;
                *(float4*)&gr[c] = o;
            }
        } else if (!hasA) {
            for (int g = tid; g < 576; g += 256) {
                int c = g * 4;
                int m = (g % 12) * 4;
                float4 bv = *(const float4*)&Bj[c];
                float c3 = (m != 44) ? Cj[c + 4] : 0.f;
                float4 o;
                o.x = bv.x + Cj[c + 1];
                o.y = bv.y + Cj[c + 2];
                o.z = bv.z + Cj[c + 3];
                o.w = bv.w + c3;
                *(float4*)&gr[c] = o;
            }
        } else {
            for (int g = tid; g < 576; g += 256) {
                int c = g * 4;
                int m = (g % 12) * 4;
                float4 bv = *(const float4*)&Bj[c];
                float a0 = (m != 0) ? Aj[c - 1] : 0.f;
                float4 o;
                o.x = a0        + bv.x;
                o.y = Aj[c]     + bv.y;
                o.z = Aj[c + 1] + bv.z;
                o.w = Aj[c + 2] + bv.w;
                *(float4*)&gr[c] = o;
            }
        }
    }
}

// ---------------- 5b) y-pass + max/argmax: S = sum_di G[lq+48di][lk+48di] ----
__global__ void maxarg_kernel(float* __restrict__ outS) {
    int b = blockIdx.y, lq = blockIdx.x;
    int yq = lq / H3;
    const float4* Gb4 = (const float4*)(g_G + (size_t)b * L3 * L3);
    const float4* z4p = (const float4*)g_zero;

    const float4* rb[3];
    bool qv[3];
    #pragma unroll
    for (int t = 0; t < 3; t++) {
        int di = t - 1;
        qv[t] = ((unsigned)(yq + di) < H3);
        rb[t] = qv[t] ? (Gb4 + (size_t)(lq + 48 * di) * 576 + 12 * di) : z4p;
    }
    const float4* rnk4 = (const float4*)&g_nrm[1][b * L3];

    float best = -1e30f; int bi = 0;
    for (int gi = threadIdx.x; gi < 576; gi += 256) {
        int yk = gi / 12;
        bool k0 = qv[0] && (yk >= 1);
        bool k2 = qv[2] && (yk <= H3 - 2);
        float4 v0 = k0 ? rb[0][gi] : *z4p;
        float4 v1 = qv[1] ? rb[1][gi] : *z4p;
        float4 v2 = k2 ? rb[2][gi] : *z4p;
        float4 rk = rnk4[gi];
        float s0 = (v0.x + v1.x + v2.x) * rk.x;
        float s1 = (v0.y + v1.y + v2.y) * rk.y;
        float s2 = (v0.z + v1.z + v2.z) * rk.z;
        float s3 = (v0.w + v1.w + v2.w) * rk.w;
        int lk = gi * 4;
        if (s0 > best) { best = s0; bi = lk; }
        if (s1 > best) { best = s1; bi = lk + 1; }
        if (s2 > best) { best = s2; bi = lk + 2; }
        if (s3 > best) { best = s3; bi = lk + 3; }
    }

    __shared__ float sv[256];
    __shared__ int   si[256];
    sv[threadIdx.x] = best; si[threadIdx.x] = bi;
    __syncthreads();
    for (int st = 128; st > 0; st >>= 1) {
        if (threadIdx.x < st) {
            float o = sv[threadIdx.x + st]; int oi = si[threadIdx.x + st];
            if (o > sv[threadIdx.x] || (o == sv[threadIdx.x] && oi < si[threadIdx.x])) {
                sv[threadIdx.x] = o; si[threadIdx.x] = oi;
            }
        }
        __syncthreads();
    }
    if (threadIdx.x == 0) {
        g_idx[b * L3 + lq] = si[0];
        outS[b * L3 + lq]  = sv[0] / g_nrm[0][b * L3 + lq];
    }
}

// ---------------- 6) fused gather + fold-normalize (precomputed cell table) --
__global__ void transfer_kernel(float* __restrict__ out, int C, int W, int ls, int sel,
                                int xpc) {
    const float* clT = (sel == 0) ? g_cl3T : (sel == 1) ? g_cl2T : g_cl1T;
    __shared__ __align__(16) float acc[3456];    // xpc*(C+8) <= 3456 floats
    __shared__ __align__(16) int4 ent[3][14];    // {dxs, base4, ok, pad}
    __shared__ float sinv[12];
    int b = blockIdx.y, y = blockIdx.x;
    int xlo = blockIdx.z * xpc;
    int tid = threadIdx.x;
    int cpg  = C >> 2;
    int cg   = tid & (cpg - 1);
    int xsub = tid / cpg;
    int ppp  = 256 / cpg;
    int astr = C + 8;

    int tyq  = y >> ls;
    int txq0 = xlo >> ls;
    const int* idxb = g_idx + b * L3;

    if (tid < 42) {
        int a = tid / 14, xi = tid % 14;
        int xq = txq0 - 1 + xi;
        int yq = tyq - 1 + a;
        int dxs = 0, base4 = 0, ok = 0;
        if ((unsigned)xq < H3 && (unsigned)yq < H3) {
            int idx = idxb[yq * H3 + xq];
            int yk = idx / H3, xk = idx % H3;
            int ys = y + ((yk - yq) << ls);
            if ((unsigned)ys < (unsigned)W) {
                ok = 1;
                base4 = ys * W * (C >> 2);
            }
            dxs = (xk - xq) << ls;
        }
        ent[a][xi] = make_int4(dxs, base4, ok, 0);
    }
    if (tid < 12) {
        int txq = txq0 + tid;
        int nvx = 1 + (txq > 0) + (txq < H3 - 1);
        int nvy = 1 + (tyq > 0) + (tyq < H3 - 1);
        sinv[tid] = 1.0f / (float)(nvx * nvy);
    }
    __syncthreads();

    const float4* f4b = (const float4*)(clT + (size_t)b * W * W * C);

    for (int xo = 0; xo < xpc; xo += ppp) {
        int x = xlo + xo + xsub;
        int xib = (x >> ls) - txq0;
        float4 sum = make_float4(0.f, 0.f, 0.f, 0.f);
        #pragma unroll
        for (int a = 0; a < 3; a++) {
            #pragma unroll
            for (int dx = 0; dx < 3; dx++) {
                int4 e = ent[a][xib + dx];
                int xs = x + e.x;
                if (e.z && (unsigned)xs < (unsigned)W) {
                    float4 v = f4b[e.y + xs * cpg + cg];
                    sum.x += v.x; sum.y += v.y; sum.z += v.z; sum.w += v.w;
                }
            }
        }
        float ic = sinv[xib];
        *(float4*)&acc[(xo + xsub) * astr + cg * 4] =
            make_float4(sum.x * ic, sum.y * ic, sum.z * ic, sum.w * ic);
    }
    __syncthreads();

    size_t ob = (size_t)b * C * W * W + (size_t)y * W + xlo;
    int tot = C * xpc;
    for (int i = tid; i < tot; i += 256) {
        int c = i / xpc, x = i % xpc;
        out[ob + (size_t)c * W * W + x] = acc[x * astr + c];
    }
}

// ---------------- launch ------------------------------------------------------
extern "C" void kernel_launch(void* const* d_in, const int* in_sizes, int n_in,
                              void* d_out, int out_size) {
    const float* img = (const float*)d_in[0];   // dh_img_lv3 [4,256,48,48]
    const float* ref = (const float*)d_in[1];   // dh_ref_lv3 [4,256,48,48]
    const float* cl1 = (const float*)d_in[2];   // cl_ref_lv1 [4,64,192,192]
    const float* cl2 = (const float*)d_in[3];   // cl_ref_lv2 [4,128,96,96]
    const float* cl3 = (const float*)d_in[4];   // cl_ref_lv3 [4,256,48,48]

    float* outS  = (float*)d_out;               // [4,1,48,48]
    float* outT3 = outS  + BB * L3;             // [4,256,48,48]
    float* outT2 = outT3 + (size_t)BB * C3 * L3;    // [4,128,96,96]
    float* outT1 = outT2 + (size_t)BB * C2 * L2n;   // [4,64,192,192]

    cudaFuncSetAttribute(gemm_kernel,
                         cudaFuncAttributeMaxDynamicSharedMemorySize, GEMM_SMEM);

    // 0: GEMM (triggers PDL dependents at start)
    gemm_kernel<<<dim3(L3 / 128, L3 / 128, BB), 256, GEMM_SMEM>>>(img, ref);

    // 1: side work (transposes + norms), PDL so it fills gemm's gaps/tail
    {
        cudaLaunchConfig_t cfg = {};
        cfg.gridDim = dim3(NSIDE);
        cfg.blockDim = dim3(256);
        cfg.dynamicSmemBytes = 0;
        cfg.stream = 0;
        cudaLaunchAttribute at;
        at.id = cudaLaunchAttributeProgrammaticStreamSerialization;
        at.val.programmaticStreamSerializationAllowed = 1;
        cfg.attrs = &at;
        cfg.numAttrs = 1;
        cudaError_t e = cudaLaunchKernelEx(&cfg, side_kernel, img, ref, cl1, cl2, cl3);
        if (e != cudaSuccess) {
            // fallback: plain launch (identical work, serialized)
            side_kernel<<<NSIDE, 256>>>(img, ref, cl1, cl2, cl3);
        }
    }

    // 2: x-pass (normal launch: full barrier on gemm + side)
    gpass1_kernel<<<dim3(L3 / 4, BB), 256>>>();

    // 3: y-pass + argmax (profiled slot)
    maxarg_kernel<<<dim3(L3, BB), 256>>>(outS);

    // 4-6: transfers
    transfer_kernel<<<dim3(H3, BB, 4), 256>>>(outT3, C3, H3, 0, 0, H3 / 4);
    transfer_kernel<<<dim3(H2, BB, 4), 256>>>(outT2, C2, H2, 1, 1, H2 / 4);
    transfer_kernel<<<dim3(H1, BB, 4), 256>>>(outT1, C1, H1, 2, 2, H1 / 4);
}